// round 6
// baseline (speedup 1.0000x reference)
#include <cuda_runtime.h>
#include <cuda_fp16.h>
#include <cstdint>

#define B_  2
#define N_  4096
#define C_  1024
#define H_  16
#define D_  64
#define K_  256
#define HD_ 1024
#define M_  8192

// ---------------- persistent split (big/small) fp16 buffers -------------
__device__ __half h_Xb [M_ * C_],    h_Xs [M_ * C_];
__device__ __half h_Wqb[HD_ * C_],   h_Wqs[HD_ * C_];
__device__ __half h_Wkb[HD_ * C_],   h_Wks[HD_ * C_];
__device__ __half h_Wvb[HD_ * C_],   h_Wvs[HD_ * C_];
__device__ __half h_Web[K_ * N_],    h_Wes[K_ * N_];
__device__ __half h_Wfb[K_ * N_],    h_Wfs[K_ * N_];
__device__ __half h_Wob[C_ * HD_],   h_Wos[C_ * HD_];
__device__ __half h_Qb [M_ * HD_],   h_Qs [M_ * HD_];
__device__ __half h_Ktb[B_ * HD_ * N_], h_Kts[B_ * HD_ * N_];
__device__ __half h_Vtb[B_ * HD_ * N_], h_Vts[B_ * HD_ * N_];
__device__ __half h_KEb[B_ * K_ * HD_], h_KEs[B_ * K_ * HD_];
__device__ __half h_VFb[B_ * HD_ * K_], h_VFs[B_ * HD_ * K_];
__device__ __half h_Ob [M_ * HD_],   h_Os [M_ * HD_];
__device__ float  g_part[8 * K_ * HD_];

#define DEV __device__ __forceinline__

DEV uint32_t su32(const void* p) {
    uint32_t a;
    asm("{ .reg .u64 t; cvta.to.shared.u64 t, %1; cvt.u32.u64 %0, t; }" : "=r"(a) : "l"(p));
    return a;
}
DEV void splitf(float x, float y, uint32_t& bo, uint32_t& so) {
    __half hx = __float2half_rn(x), hy = __float2half_rn(y);
    __half2 hb = __halves2half2(hx, hy);
    bo = *(uint32_t*)&hb;
    __half2 hs = __floats2half2_rn(x - __half2float(hx), y - __half2float(hy));
    so = *(uint32_t*)&hs;
}

#define CP16(dst, src) asm volatile("cp.async.cg.shared.global [%0], [%1], 16;" :: "r"(dst), "l"(src) : "memory")
#define CPCOMMIT() asm volatile("cp.async.commit_group;" ::: "memory")
#define CPWAIT(n)  asm volatile("cp.async.wait_group %0;" :: "n"(n) : "memory")

#define LDM4(r, a) \
    asm volatile("ldmatrix.sync.aligned.m8n8.x4.shared.b16 {%0,%1,%2,%3}, [%4];" \
        : "=r"((r)[0]), "=r"((r)[1]), "=r"((r)[2]), "=r"((r)[3]) : "r"(a))

DEV void mma16816(float* d, const uint32_t* a, const uint32_t* b) {
    asm volatile("mma.sync.aligned.m16n8k16.row.col.f32.f16.f16.f32 "
        "{%0,%1,%2,%3}, {%4,%5,%6,%7}, {%8,%9}, {%0,%1,%2,%3};"
        : "+f"(d[0]), "+f"(d[1]), "+f"(d[2]), "+f"(d[3])
        : "r"(a[0]), "r"(a[1]), "r"(a[2]), "r"(a[3]), "r"(b[0]), "r"(b[1]));
}

// swizzled byte offset inside a 128x32-half tile (rows of 64B, 16B chunks)
DEV uint32_t tswz(int r, int ch) { return (r << 6) | (((ch ^ ((r >> 1) & 3)) & 3) << 4); }

// ==========================================================================
// split pass: fp32 array -> (big, small) fp16 arrays
// ==========================================================================
__global__ void split_arr(const float* __restrict__ in, __half* __restrict__ ob,
                          __half* __restrict__ os, int n4)
{
    const int i = blockIdx.x * 256 + threadIdx.x;
    if (i >= n4) return;
    float4 v = ((const float4*)in)[i];
    uint32_t b0, s0, b1, s1;
    splitf(v.x, v.y, b0, s0);
    splitf(v.z, v.w, b1, s1);
    ((uint2*)ob)[i] = make_uint2(b0, b1);
    ((uint2*)os)[i] = make_uint2(s0, s1);
}

// ==========================================================================
// fp16 split-GEMM: C[M,N] = (Ab+As)[M,K] * (Bb+Bs)[N,K]^T  (3-term)
// 128x128 tile, BK=32, 256 thr, warp tile 64x32, cp.async 4-stage, swizzled
// EPI: 0 = fp32 out (+opt col bias), 1 = split-half pair out
// ==========================================================================
#define GEMM_SMEM 131072   // 4 stages x 32 KB

template<int EPI, int BIASCOL>
__global__ void __launch_bounds__(256)
hgemm(const __half* __restrict__ Ab_, const __half* __restrict__ As_,
      const __half* __restrict__ Bb_, const __half* __restrict__ Bs_,
      const float* __restrict__ bias, float* __restrict__ Cf,
      __half* __restrict__ Cbh, __half* __restrict__ Csh,
      int ldA, int ldB, int ldC, int Kdim,
      long zA, long zB, long zC, int splitk)
{
    extern __shared__ __half sh[];
    const int tid = threadIdx.x, wid = tid >> 5, lane = tid & 31;
    const uint32_t shb = su32(sh);

    long aOff, bOff, cOff;
    if (splitk) {
        int zb = blockIdx.z >> 2, ks = blockIdx.z & 3;
        aOff = (long)zb * zA + ks * 1024;
        bOff = (long)zb * zB + ks * 1024;
        cOff = (long)blockIdx.z * zC;
    } else {
        aOff = (long)blockIdx.z * zA;
        bOff = (long)blockIdx.z * zB;
        cOff = (long)blockIdx.z * zC;
    }
    const __half* Agb = Ab_ + aOff + (size_t)(blockIdx.y * 128) * ldA;
    const __half* Ags = As_ + aOff + (size_t)(blockIdx.y * 128) * ldA;
    const __half* Bgb = Bb_ + bOff + (size_t)(blockIdx.x * 128) * ldB;
    const __half* Bgs = Bs_ + bOff + (size_t)(blockIdx.x * 128) * ldB;

    const int wm = (wid >> 2) * 64, wn = (wid & 3) * 32;

    float acc[4][4][4];
#pragma unroll
    for (int m = 0; m < 4; m++)
#pragma unroll
        for (int n = 0; n < 4; n++)
#pragma unroll
            for (int j = 0; j < 4; j++) acc[m][n][j] = 0.f;

    // stage layout (bytes): Ab@0, As@8192, Bb@16384, Bs@24576; stage stride 32768
    auto PREFETCH = [&](int kt, int s) {
        const uint32_t st = shb + s * 32768;
        const int kc = kt * 32;
#pragma unroll
        for (int p = 0; p < 2; p++) {
            const int id = p * 256 + tid;
            const int r = id >> 2, c = id & 3;
            const uint32_t d = st + tswz(r, c);
            const size_t ga = (size_t)r * ldA + kc + c * 8;
            const size_t gb = (size_t)r * ldB + kc + c * 8;
            CP16(d,         Agb + ga);
            CP16(d +  8192, Ags + ga);
            CP16(d + 16384, Bgb + gb);
            CP16(d + 24576, Bgs + gb);
        }
    };

    auto COMPUTE = [&](int s) {
        const uint32_t base = shb + s * 32768;
#pragma unroll
        for (int ks2 = 0; ks2 < 2; ks2++) {
            uint32_t ab[4][4], as_[4][4];
#pragma unroll
            for (int m = 0; m < 4; m++) {
                const int r = wm + m * 16 + (lane & 15);
                const int ch = ks2 * 2 + (lane >> 4);
                const uint32_t ad = base + tswz(r, ch);
                LDM4(ab[m], ad);
                LDM4(as_[m], ad + 8192);
            }
#pragma unroll
            for (int np = 0; np < 2; np++) {
                const int r = wn + np * 16 + (lane & 7) + 8 * (lane >> 4);
                const int ch = ks2 * 2 + ((lane >> 3) & 1);
                const uint32_t bd = base + 16384 + tswz(r, ch);
                uint32_t bb[4], bs[4];
                LDM4(bb, bd);
                LDM4(bs, bd + 8192);
#pragma unroll
                for (int m = 0; m < 4; m++) {
                    mma16816(acc[m][2 * np],     ab[m],  bb);
                    mma16816(acc[m][2 * np],     ab[m],  bs);
                    mma16816(acc[m][2 * np],     as_[m], bb);
                    mma16816(acc[m][2 * np + 1], ab[m],  bb + 2);
                    mma16816(acc[m][2 * np + 1], ab[m],  bs + 2);
                    mma16816(acc[m][2 * np + 1], as_[m], bb + 2);
                }
            }
        }
    };

    const int NK = Kdim >> 5;
    PREFETCH(0, 0); CPCOMMIT();
    PREFETCH(1, 1); CPCOMMIT();
    PREFETCH(2, 2); CPCOMMIT();
    for (int kt = 0; kt < NK; kt++) {
        CPWAIT(2);
        __syncthreads();
        if (kt + 3 < NK) { PREFETCH(kt + 3, (kt + 3) & 3); CPCOMMIT(); }
        COMPUTE(kt & 3);
    }

    const int row0 = blockIdx.y * 128 + wm + (lane >> 2);
    const int col0 = blockIdx.x * 128 + wn + 2 * (lane & 3);
#pragma unroll
    for (int m = 0; m < 4; m++) {
#pragma unroll
        for (int n = 0; n < 4; n++) {
            const int r = row0 + m * 16, c = col0 + n * 8;
            float v0 = acc[m][n][0], v1 = acc[m][n][1];
            float v2 = acc[m][n][2], v3 = acc[m][n][3];
            if (EPI == 0) {
                if (BIASCOL) {
                    const float bc0 = __ldg(&bias[c]), bc1 = __ldg(&bias[c + 1]);
                    v0 += bc0; v1 += bc1; v2 += bc0; v3 += bc1;
                }
                float* Cg = Cf + cOff;
                *(float2*)&Cg[(size_t)r * ldC + c]       = make_float2(v0, v1);
                *(float2*)&Cg[(size_t)(r + 8) * ldC + c] = make_float2(v2, v3);
            } else {
                __half* Cb = Cbh + cOff;
                __half* Cs = Csh + cOff;
                uint32_t b0, s0, b1, s1;
                splitf(v0, v1, b0, s0);
                splitf(v2, v3, b1, s1);
                *(uint32_t*)&Cb[(size_t)r * ldC + c]       = b0;
                *(uint32_t*)&Cs[(size_t)r * ldC + c]       = s0;
                *(uint32_t*)&Cb[(size_t)(r + 8) * ldC + c] = b1;
                *(uint32_t*)&Cs[(size_t)(r + 8) * ldC + c] = s1;
            }
        }
    }
}

// ==========================================================================
// split-K reduce + bias -> split halves
// ==========================================================================
__global__ void reduce_split(const float* __restrict__ part, const float* __restrict__ bias,
                             __half* __restrict__ ob, __half* __restrict__ os,
                             int cols, int biasCol)
{
    const int per = (K_ * HD_) / 4;
    const int i = blockIdx.x * 256 + threadIdx.x;
    const int b = blockIdx.y;
    const float4* p = (const float4*)part + (size_t)b * 4 * per;
    float4 v = p[i];
    float4 v1 = p[per + i], v2 = p[2 * per + i], v3 = p[3 * per + i];
    v.x += v1.x + v2.x + v3.x; v.y += v1.y + v2.y + v3.y;
    v.z += v1.z + v2.z + v3.z; v.w += v1.w + v2.w + v3.w;
    const int e = i * 4;
    if (biasCol) {
        const int c = e % cols;
        v.x += bias[c]; v.y += bias[c + 1]; v.z += bias[c + 2]; v.w += bias[c + 3];
    } else {
        const float bb = bias[e / cols];
        v.x += bb; v.y += bb; v.z += bb; v.w += bb;
    }
    uint32_t b0, s0, b1, s1;
    splitf(v.x, v.y, b0, s0);
    splitf(v.z, v.w, b1, s1);
    ((uint2*)ob)[(size_t)b * per + i] = make_uint2(b0, b1);
    ((uint2*)os)[(size_t)b * per + i] = make_uint2(s0, s1);
}

// ==========================================================================
// Fused attention: CTA = (128 rows, head h, batch b), 8 warps
// ==========================================================================
#define QSTR 72
#define VSTR 264
#define OQB 0
#define OQS (128 * QSTR)
#define OKB (2 * 128 * QSTR)
#define OKS (OKB + 256 * QSTR)
#define OVB (OKS + 256 * QSTR)
#define OVS (OVB + 64 * VSTR)
#define ATT_SMEM ((OVS + 64 * VSTR) * 2)

__global__ void __launch_bounds__(256, 1)
attn_mma(const __half* __restrict__ Qb, const __half* __restrict__ Qs,
         const __half* __restrict__ KEb, const __half* __restrict__ KEs,
         const __half* __restrict__ VFb, const __half* __restrict__ VFs,
         __half* __restrict__ Ob, __half* __restrict__ Os)
{
    extern __shared__ __half sh[];
    const int tid = threadIdx.x, wid = tid >> 5, lane = tid & 31;
    const int b = blockIdx.z, h = blockIdx.y, n0 = blockIdx.x * 128;
    const uint32_t shb = su32(sh);

    const __half* Qgb = Qb  + ((size_t)(b * N_ + n0)) * HD_ + h * D_;
    const __half* Qgs = Qs  + ((size_t)(b * N_ + n0)) * HD_ + h * D_;
    const __half* Kgb = KEb + ((size_t)b * K_) * HD_ + h * D_;
    const __half* Kgs = KEs + ((size_t)b * K_) * HD_ + h * D_;
    const __half* Vgb = VFb + ((size_t)(b * HD_ + h * D_)) * K_;
    const __half* Vgs = VFs + ((size_t)(b * HD_ + h * D_)) * K_;

#pragma unroll
    for (int p = 0; p < 4; p++) {         // Q: 128 rows x 8 chunks
        const int id = p * 256 + tid;
        const int r = id >> 3, c = id & 7;
        const size_t g = (size_t)r * HD_ + c * 8;
        const uint32_t d = (r * QSTR + c * 8) * 2;
        CP16(shb + OQB * 2 + d, Qgb + g);
        CP16(shb + OQS * 2 + d, Qgs + g);
    }
#pragma unroll
    for (int p = 0; p < 8; p++) {         // KE: 256 rows x 8 chunks
        const int id = p * 256 + tid;
        const int r = id >> 3, c = id & 7;
        const size_t g = (size_t)r * HD_ + c * 8;
        const uint32_t d = (r * QSTR + c * 8) * 2;
        CP16(shb + OKB * 2 + d, Kgb + g);
        CP16(shb + OKS * 2 + d, Kgs + g);
    }
#pragma unroll
    for (int p = 0; p < 8; p++) {         // VF: 64 rows x 32 chunks
        const int id = p * 256 + tid;
        const int r = id >> 5, c = id & 31;
        const size_t g = (size_t)r * K_ + c * 8;
        const uint32_t d = (r * VSTR + c * 8) * 2;
        CP16(shb + OVB * 2 + d, Vgb + g);
        CP16(shb + OVS * 2 + d, Vgs + g);
    }
    CPCOMMIT();
    CPWAIT(0);
    __syncthreads();

    // ---- scores
    float sacc[32][4];
#pragma unroll
    for (int j = 0; j < 32; j++)
#pragma unroll
        for (int q = 0; q < 4; q++) sacc[j][q] = 0.f;

    const int r0 = wid * 16;
    const uint32_t aoff = ((r0 + (lane & 15)) * QSTR + 8 * (lane >> 4)) * 2;
    const uint32_t boff = (((lane & 7) + 8 * (lane >> 4)) * QSTR + 8 * ((lane >> 3) & 1)) * 2;

#pragma unroll
    for (int ks = 0; ks < 64; ks += 16) {
        uint32_t ab[4], as_[4];
        LDM4(ab,  shb + OQB * 2 + aoff + ks * 2);
        LDM4(as_, shb + OQS * 2 + aoff + ks * 2);
#pragma unroll
        for (int np = 0; np < 16; np++) {
            uint32_t kb[4], ksm[4];
            const uint32_t bd = boff + (np * 16 * QSTR + ks) * 2;
            LDM4(kb,  shb + OKB * 2 + bd);
            LDM4(ksm, shb + OKS * 2 + bd);
            mma16816(sacc[2 * np],     ab,  kb);
            mma16816(sacc[2 * np],     ab,  ksm);
            mma16816(sacc[2 * np],     as_, kb);
            mma16816(sacc[2 * np + 1], ab,  kb + 2);
            mma16816(sacc[2 * np + 1], ab,  ksm + 2);
            mma16816(sacc[2 * np + 1], as_, kb + 2);
        }
    }

    // ---- softmax
    float mx0 = -1e30f, mx1 = -1e30f;
#pragma unroll
    for (int j = 0; j < 32; j++) {
        mx0 = fmaxf(mx0, fmaxf(sacc[j][0], sacc[j][1]));
        mx1 = fmaxf(mx1, fmaxf(sacc[j][2], sacc[j][3]));
    }
    mx0 = fmaxf(mx0, __shfl_xor_sync(0xffffffffu, mx0, 1));
    mx0 = fmaxf(mx0, __shfl_xor_sync(0xffffffffu, mx0, 2));
    mx1 = fmaxf(mx1, __shfl_xor_sync(0xffffffffu, mx1, 1));
    mx1 = fmaxf(mx1, __shfl_xor_sync(0xffffffffu, mx1, 2));
    float sum0 = 0.f, sum1 = 0.f;
#pragma unroll
    for (int j = 0; j < 32; j++) {
        float e0 = __expf((sacc[j][0] - mx0) * 0.125f);
        float e1 = __expf((sacc[j][1] - mx0) * 0.125f);
        float e2 = __expf((sacc[j][2] - mx1) * 0.125f);
        float e3 = __expf((sacc[j][3] - mx1) * 0.125f);
        sacc[j][0] = e0; sacc[j][1] = e1; sacc[j][2] = e2; sacc[j][3] = e3;
        sum0 += e0 + e1; sum1 += e2 + e3;
    }
    sum0 += __shfl_xor_sync(0xffffffffu, sum0, 1);
    sum0 += __shfl_xor_sync(0xffffffffu, sum0, 2);
    sum1 += __shfl_xor_sync(0xffffffffu, sum1, 1);
    sum1 += __shfl_xor_sync(0xffffffffu, sum1, 2);
    const float inv0 = 1.0f / sum0, inv1 = 1.0f / sum1;
#pragma unroll
    for (int j = 0; j < 32; j++) {
        sacc[j][0] *= inv0; sacc[j][1] *= inv0;
        sacc[j][2] *= inv1; sacc[j][3] *= inv1;
    }

    // ---- PV
    float oacc[8][4];
#pragma unroll
    for (int n = 0; n < 8; n++)
#pragma unroll
        for (int q = 0; q < 4; q++) oacc[n][q] = 0.f;

#pragma unroll
    for (int kt = 0; kt < 16; kt++) {
        uint32_t pa[4], ps[4];
        splitf(sacc[2 * kt][0],     sacc[2 * kt][1],     pa[0], ps[0]);
        splitf(sacc[2 * kt][2],     sacc[2 * kt][3],     pa[1], ps[1]);
        splitf(sacc[2 * kt + 1][0], sacc[2 * kt + 1][1], pa[2], ps[2]);
        splitf(sacc[2 * kt + 1][2], sacc[2 * kt + 1][3], pa[3], ps[3]);
#pragma unroll
        for (int np = 0; np < 4; np++) {
            const uint32_t bd = (((lane & 7) + 8 * (lane >> 4) + np * 16) * VSTR
                                 + kt * 16 + 8 * ((lane >> 3) & 1)) * 2;
            uint32_t vb[4], vs[4];
            LDM4(vb, shb + OVB * 2 + bd);
            LDM4(vs, shb + OVS * 2 + bd);
            mma16816(oacc[2 * np],     pa, vb);
            mma16816(oacc[2 * np],     pa, vs);
            mma16816(oacc[2 * np],     ps, vb);
            mma16816(oacc[2 * np + 1], pa, vb + 2);
            mma16816(oacc[2 * np + 1], pa, vs + 2);
            mma16816(oacc[2 * np + 1], ps, vb + 2);
        }
    }

    // ---- store O as split halves
    const int orow = n0 + r0 + (lane >> 2);
    const int ocol = h * D_ + 2 * (lane & 3);
    __half* Obp = Ob + ((size_t)b * N_) * HD_;
    __half* Osp = Os + ((size_t)b * N_) * HD_;
#pragma unroll
    for (int n = 0; n < 8; n++) {
        uint32_t b0, s0, b1, s1;
        splitf(oacc[n][0], oacc[n][1], b0, s0);
        splitf(oacc[n][2], oacc[n][3], b1, s1);
        *(uint32_t*)&Obp[(size_t)orow * HD_ + ocol + n * 8]       = b0;
        *(uint32_t*)&Osp[(size_t)orow * HD_ + ocol + n * 8]       = s0;
        *(uint32_t*)&Obp[(size_t)(orow + 8) * HD_ + ocol + n * 8] = b1;
        *(uint32_t*)&Osp[(size_t)(orow + 8) * HD_ + ocol + n * 8] = s1;
    }
}

// ==========================================================================
extern "C" void kernel_launch(void* const* d_in, const int* in_sizes, int n_in,
                              void* d_out, int out_size)
{
    const float* X  = (const float*)d_in[0];
    const float* Wq = (const float*)d_in[1];
    const float* Wk = (const float*)d_in[2];
    const float* Wv = (const float*)d_in[3];
    const float* We = (const float*)d_in[4];
    const float* be = (const float*)d_in[5];
    const float* Wf = (const float*)d_in[6];
    const float* bf = (const float*)d_in[7];
    const float* Wo = (const float*)d_in[8];
    const float* bo = (const float*)d_in[9];
    float* out = (float*)d_out;

    __half *Xb, *Xs, *Wqb, *Wqs, *Wkb, *Wks, *Wvb, *Wvs, *Web, *Wes, *Wfb, *Wfs, *Wob, *Wos;
    __half *Qb, *Qs, *Ktb, *Kts, *Vtb, *Vts, *KEbp, *KEsp, *VFbp, *VFsp, *Obp, *Osp;
    float* Pp;
    cudaGetSymbolAddress((void**)&Xb,  h_Xb);  cudaGetSymbolAddress((void**)&Xs,  h_Xs);
    cudaGetSymbolAddress((void**)&Wqb, h_Wqb); cudaGetSymbolAddress((void**)&Wqs, h_Wqs);
    cudaGetSymbolAddress((void**)&Wkb, h_Wkb); cudaGetSymbolAddress((void**)&Wks, h_Wks);
    cudaGetSymbolAddress((void**)&Wvb, h_Wvb); cudaGetSymbolAddress((void**)&Wvs, h_Wvs);
    cudaGetSymbolAddress((void**)&Web, h_Web); cudaGetSymbolAddress((void**)&Wes, h_Wes);
    cudaGetSymbolAddress((void**)&Wfb, h_Wfb); cudaGetSymbolAddress((void**)&Wfs, h_Wfs);
    cudaGetSymbolAddress((void**)&Wob, h_Wob); cudaGetSymbolAddress((void**)&Wos, h_Wos);
    cudaGetSymbolAddress((void**)&Qb,  h_Qb);  cudaGetSymbolAddress((void**)&Qs,  h_Qs);
    cudaGetSymbolAddress((void**)&Ktb, h_Ktb); cudaGetSymbolAddress((void**)&Kts, h_Kts);
    cudaGetSymbolAddress((void**)&Vtb, h_Vtb); cudaGetSymbolAddress((void**)&Vts, h_Vts);
    cudaGetSymbolAddress((void**)&KEbp, h_KEb); cudaGetSymbolAddress((void**)&KEsp, h_KEs);
    cudaGetSymbolAddress((void**)&VFbp, h_VFb); cudaGetSymbolAddress((void**)&VFsp, h_VFs);
    cudaGetSymbolAddress((void**)&Obp, h_Ob);  cudaGetSymbolAddress((void**)&Osp, h_Os);
    cudaGetSymbolAddress((void**)&Pp,  g_part);

    cudaFuncSetAttribute(hgemm<0, 0>, cudaFuncAttributeMaxDynamicSharedMemorySize, GEMM_SMEM);
    cudaFuncSetAttribute(hgemm<0, 1>, cudaFuncAttributeMaxDynamicSharedMemorySize, GEMM_SMEM);
    cudaFuncSetAttribute(hgemm<1, 0>, cudaFuncAttributeMaxDynamicSharedMemorySize, GEMM_SMEM);
    cudaFuncSetAttribute(attn_mma, cudaFuncAttributeMaxDynamicSharedMemorySize, ATT_SMEM);

    // ---- pre-split inputs
    split_arr<<<(M_ * C_ / 4 + 255) / 256, 256>>>(X,  Xb,  Xs,  M_ * C_ / 4);
    split_arr<<<(HD_ * C_ / 4 + 255) / 256, 256>>>(Wq, Wqb, Wqs, HD_ * C_ / 4);
    split_arr<<<(HD_ * C_ / 4 + 255) / 256, 256>>>(Wk, Wkb, Wks, HD_ * C_ / 4);
    split_arr<<<(HD_ * C_ / 4 + 255) / 256, 256>>>(Wv, Wvb, Wvs, HD_ * C_ / 4);
    split_arr<<<(K_ * N_ / 4 + 255) / 256, 256>>>(We, Web, Wes, K_ * N_ / 4);
    split_arr<<<(K_ * N_ / 4 + 255) / 256, 256>>>(Wf, Wfb, Wfs, K_ * N_ / 4);
    split_arr<<<(C_ * HD_ / 4 + 255) / 256, 256>>>(Wo, Wob, Wos, C_ * HD_ / 4);

    // ---- Q = X * Wq^T -> split halves           [8192, 1024]
    hgemm<1, 0><<<dim3(8, 64, 1), 256, GEMM_SMEM>>>(Xb, Xs, Wqb, Wqs, nullptr,
        nullptr, Qb, Qs, 1024, 1024, 1024, 1024, 0, 0, 0, 0);
    // ---- Kt[b] = Wk * X_b^T -> halves           [1024, 4096] per b
    hgemm<1, 0><<<dim3(32, 8, B_), 256, GEMM_SMEM>>>(Wkb, Wks, Xb, Xs, nullptr,
        nullptr, Ktb, Kts, 1024, 1024, 4096, 1024, 0, (long)N_ * C_, (long)HD_ * N_, 0);
    // ---- Vt[b] = Wv * X_b^T -> halves
    hgemm<1, 0><<<dim3(32, 8, B_), 256, GEMM_SMEM>>>(Wvb, Wvs, Xb, Xs, nullptr,
        nullptr, Vtb, Vts, 1024, 1024, 4096, 1024, 0, (long)N_ * C_, (long)HD_ * N_, 0);
    // ---- KE partials (split-K x4): We * Kt^T -> fp32   [256, 1024]
    hgemm<0, 0><<<dim3(8, 2, 8), 256, GEMM_SMEM>>>(Web, Wes, Ktb, Kts, nullptr,
        Pp, nullptr, nullptr, 4096, 4096, 1024, 1024, 0, (long)HD_ * N_, (long)K_ * HD_, 1);
    reduce_split<<<dim3((K_ * HD_ / 4) / 256, B_), 256>>>(Pp, be, KEbp, KEsp, HD_, 0);
    // ---- VFt partials (split-K x4): Vt * Wf^T -> fp32  [1024, 256]
    hgemm<0, 0><<<dim3(2, 8, 8), 256, GEMM_SMEM>>>(Vtb, Vts, Wfb, Wfs, nullptr,
        Pp, nullptr, nullptr, 4096, 4096, 256, 1024, (long)HD_ * N_, 0, (long)HD_ * K_, 1);
    reduce_split<<<dim3((HD_ * K_ / 4) / 256, B_), 256>>>(Pp, bf, VFbp, VFsp, K_, 1);
    // ---- fused attention -> O halves
    attn_mma<<<dim3(N_ / 128, H_, B_), 256, ATT_SMEM>>>(Qb, Qs, KEbp, KEsp, VFbp, VFsp, Obp, Osp);
    // ---- out = O * Wo^T + bo                     [8192, 1024] fp32
    hgemm<0, 1><<<dim3(8, 64, 1), 256, GEMM_SMEM>>>(Obp, Osp, Wob, Wos, bo,
        out, nullptr, nullptr, 1024, 1024, 1024, 1024, 0, 0, 0, 0);
}

// round 7
// speedup vs baseline: 1.1142x; 1.1142x over previous
#include <cuda_runtime.h>
#include <cuda_fp16.h>
#include <cstdint>

#define B_  2
#define N_  4096
#define C_  1024
#define H_  16
#define D_  64
#define K_  256
#define HD_ 1024
#define M_  8192

// ---------------- persistent split (big/small) fp16 buffers -------------
__device__ __half h_Xb [M_ * C_],    h_Xs [M_ * C_];
__device__ __half h_Wqb[HD_ * C_],   h_Wqs[HD_ * C_];
__device__ __half h_Wkb[HD_ * C_],   h_Wks[HD_ * C_];
__device__ __half h_Wvb[HD_ * C_],   h_Wvs[HD_ * C_];
__device__ __half h_Web[K_ * N_],    h_Wes[K_ * N_];
__device__ __half h_Wfb[K_ * N_],    h_Wfs[K_ * N_];
__device__ __half h_Wob[C_ * HD_],   h_Wos[C_ * HD_];
__device__ __half h_Qb [M_ * HD_],   h_Qs [M_ * HD_];
__device__ __half h_Ktb[B_ * HD_ * N_], h_Kts[B_ * HD_ * N_];
__device__ __half h_Vtb[B_ * HD_ * N_], h_Vts[B_ * HD_ * N_];
__device__ __half h_KEb[B_ * K_ * HD_], h_KEs[B_ * K_ * HD_];
__device__ __half h_VFb[B_ * HD_ * K_], h_VFs[B_ * HD_ * K_];
__device__ __half h_Ob [M_ * HD_],   h_Os [M_ * HD_];
__device__ float  g_part[8 * K_ * HD_];

#define DEV __device__ __forceinline__

DEV uint32_t su32(const void* p) {
    uint32_t a;
    asm("{ .reg .u64 t; cvta.to.shared.u64 t, %1; cvt.u32.u64 %0, t; }" : "=r"(a) : "l"(p));
    return a;
}
DEV void splitf(float x, float y, uint32_t& bo, uint32_t& so) {
    __half hx = __float2half_rn(x), hy = __float2half_rn(y);
    __half2 hb = __halves2half2(hx, hy);
    bo = *(uint32_t*)&hb;
    __half2 hs = __floats2half2_rn(x - __half2float(hx), y - __half2float(hy));
    so = *(uint32_t*)&hs;
}

#define CP16(dst, src) asm volatile("cp.async.cg.shared.global [%0], [%1], 16;" :: "r"(dst), "l"(src) : "memory")
#define CPCOMMIT() asm volatile("cp.async.commit_group;" ::: "memory")
#define CPWAIT(n)  asm volatile("cp.async.wait_group %0;" :: "n"(n) : "memory")

#define LDM4(r, a) \
    asm volatile("ldmatrix.sync.aligned.m8n8.x4.shared.b16 {%0,%1,%2,%3}, [%4];" \
        : "=r"((r)[0]), "=r"((r)[1]), "=r"((r)[2]), "=r"((r)[3]) : "r"(a))

DEV void mma16816(float* d, const uint32_t* a, const uint32_t* b) {
    asm volatile("mma.sync.aligned.m16n8k16.row.col.f32.f16.f16.f32 "
        "{%0,%1,%2,%3}, {%4,%5,%6,%7}, {%8,%9}, {%0,%1,%2,%3};"
        : "+f"(d[0]), "+f"(d[1]), "+f"(d[2]), "+f"(d[3])
        : "r"(a[0]), "r"(a[1]), "r"(a[2]), "r"(a[3]), "r"(b[0]), "r"(b[1]));
}

// swizzled byte offset inside a 128x32-half tile (rows of 64B, 16B chunks)
DEV uint32_t tswz(int r, int ch) { return (r << 6) | (((ch ^ ((r >> 1) & 3)) & 3) << 4); }

// ==========================================================================
// split passes: fp32 -> (big, small) fp16
// ==========================================================================
__global__ void split_arr(const float* __restrict__ in, __half* __restrict__ ob,
                          __half* __restrict__ os, int n4)
{
    const int i = blockIdx.x * 256 + threadIdx.x;
    if (i >= n4) return;
    float4 v = ((const float4*)in)[i];
    uint32_t b0, s0, b1, s1;
    splitf(v.x, v.y, b0, s0);
    splitf(v.z, v.w, b1, s1);
    ((uint2*)ob)[i] = make_uint2(b0, b1);
    ((uint2*)os)[i] = make_uint2(s0, s1);
}

// six equal-size (1M element) weight arrays in one launch; grid.y selects
__global__ void split6(const float* w0, __half* b0, __half* s0,
                       const float* w1, __half* b1, __half* s1,
                       const float* w2, __half* b2, __half* s2,
                       const float* w3, __half* b3, __half* s3,
                       const float* w4, __half* b4, __half* s4,
                       const float* w5, __half* b5, __half* s5)
{
    const int y = blockIdx.y;
    const float* in = (y == 0) ? w0 : (y == 1) ? w1 : (y == 2) ? w2
                    : (y == 3) ? w3 : (y == 4) ? w4 : w5;
    __half* ob = (y == 0) ? b0 : (y == 1) ? b1 : (y == 2) ? b2
               : (y == 3) ? b3 : (y == 4) ? b4 : b5;
    __half* os = (y == 0) ? s0 : (y == 1) ? s1 : (y == 2) ? s2
               : (y == 3) ? s3 : (y == 4) ? s4 : s5;
    const int i = blockIdx.x * 256 + threadIdx.x;
    float4 v = ((const float4*)in)[i];
    uint32_t c0, d0, c1, d1;
    splitf(v.x, v.y, c0, d0);
    splitf(v.z, v.w, c1, d1);
    ((uint2*)ob)[i] = make_uint2(c0, c1);
    ((uint2*)os)[i] = make_uint2(d0, d1);
}

// ==========================================================================
// fp16 split-GEMM: C[M,N] = (Ab+As)[M,K] * (Bb+Bs)[N,K]^T  (3-term)
// 128x128 tile, BK=32, 256 thr, warp tile 64x32, cp.async 3-stage, swizzled
// 2 CTAs/SM resident (96 KB smem, 128-reg cap)
// ==========================================================================
#define GEMM_SMEM 98304   // 3 stages x 32 KB

template<int EPI, int BIASCOL>
__global__ void __launch_bounds__(256, 2)
hgemm(const __half* __restrict__ Ab_, const __half* __restrict__ As_,
      const __half* __restrict__ Bb_, const __half* __restrict__ Bs_,
      const float* __restrict__ bias, float* __restrict__ Cf,
      __half* __restrict__ Cbh, __half* __restrict__ Csh,
      int ldA, int ldB, int ldC, int Kdim,
      long zA, long zB, long zC, int splitk)
{
    extern __shared__ __half sh[];
    const int tid = threadIdx.x, wid = tid >> 5, lane = tid & 31;
    const uint32_t shb = su32(sh);

    long aOff, bOff, cOff;
    if (splitk) {
        int zb = blockIdx.z >> 2, ks = blockIdx.z & 3;
        aOff = (long)zb * zA + ks * 1024;
        bOff = (long)zb * zB + ks * 1024;
        cOff = (long)blockIdx.z * zC;
    } else {
        aOff = (long)blockIdx.z * zA;
        bOff = (long)blockIdx.z * zB;
        cOff = (long)blockIdx.z * zC;
    }
    const __half* Agb = Ab_ + aOff + (size_t)(blockIdx.y * 128) * ldA;
    const __half* Ags = As_ + aOff + (size_t)(blockIdx.y * 128) * ldA;
    const __half* Bgb = Bb_ + bOff + (size_t)(blockIdx.x * 128) * ldB;
    const __half* Bgs = Bs_ + bOff + (size_t)(blockIdx.x * 128) * ldB;

    const int wm = (wid >> 2) * 64, wn = (wid & 3) * 32;

    float acc[4][4][4];
#pragma unroll
    for (int m = 0; m < 4; m++)
#pragma unroll
        for (int n = 0; n < 4; n++)
#pragma unroll
            for (int j = 0; j < 4; j++) acc[m][n][j] = 0.f;

    // stage layout (bytes): Ab@0, As@8192, Bb@16384, Bs@24576; stage stride 32768
    auto PREFETCH = [&](int kt, int s) {
        const uint32_t st = shb + s * 32768;
        const int kc = kt * 32;
#pragma unroll
        for (int p = 0; p < 2; p++) {
            const int id = p * 256 + tid;
            const int r = id >> 2, c = id & 3;
            const uint32_t d = st + tswz(r, c);
            const size_t ga = (size_t)r * ldA + kc + c * 8;
            const size_t gb = (size_t)r * ldB + kc + c * 8;
            CP16(d,         Agb + ga);
            CP16(d +  8192, Ags + ga);
            CP16(d + 16384, Bgb + gb);
            CP16(d + 24576, Bgs + gb);
        }
    };

    auto COMPUTE = [&](int s) {
        const uint32_t base = shb + s * 32768;
#pragma unroll
        for (int ks2 = 0; ks2 < 2; ks2++) {
            uint32_t ab[4][4], as_[4][4];
#pragma unroll
            for (int m = 0; m < 4; m++) {
                const int r = wm + m * 16 + (lane & 15);
                const int ch = ks2 * 2 + (lane >> 4);
                const uint32_t ad = base + tswz(r, ch);
                LDM4(ab[m], ad);
                LDM4(as_[m], ad + 8192);
            }
#pragma unroll
            for (int np = 0; np < 2; np++) {
                const int r = wn + np * 16 + (lane & 7) + 8 * (lane >> 4);
                const int ch = ks2 * 2 + ((lane >> 3) & 1);
                const uint32_t bd = base + 16384 + tswz(r, ch);
                uint32_t bb[4], bs[4];
                LDM4(bb, bd);
                LDM4(bs, bd + 8192);
#pragma unroll
                for (int m = 0; m < 4; m++) {
                    mma16816(acc[m][2 * np],     ab[m],  bb);
                    mma16816(acc[m][2 * np],     ab[m],  bs);
                    mma16816(acc[m][2 * np],     as_[m], bb);
                    mma16816(acc[m][2 * np + 1], ab[m],  bb + 2);
                    mma16816(acc[m][2 * np + 1], ab[m],  bs + 2);
                    mma16816(acc[m][2 * np + 1], as_[m], bb + 2);
                }
            }
        }
    };

    const int NK = Kdim >> 5;
    PREFETCH(0, 0); CPCOMMIT();
    PREFETCH(1, 1); CPCOMMIT();
    int sc = 0, sp = 2;
    for (int kt = 0; kt < NK; kt++) {
        if (kt + 2 < NK) CPWAIT(1); else CPWAIT(0);
        __syncthreads();
        if (kt + 2 < NK) { PREFETCH(kt + 2, sp); CPCOMMIT(); }
        COMPUTE(sc);
        sc = (sc == 2) ? 0 : sc + 1;
        sp = (sp == 2) ? 0 : sp + 1;
    }

    const int row0 = blockIdx.y * 128 + wm + (lane >> 2);
    const int col0 = blockIdx.x * 128 + wn + 2 * (lane & 3);
#pragma unroll
    for (int m = 0; m < 4; m++) {
#pragma unroll
        for (int n = 0; n < 4; n++) {
            const int r = row0 + m * 16, c = col0 + n * 8;
            float v0 = acc[m][n][0], v1 = acc[m][n][1];
            float v2 = acc[m][n][2], v3 = acc[m][n][3];
            if (EPI == 0) {
                if (BIASCOL) {
                    const float bc0 = __ldg(&bias[c]), bc1 = __ldg(&bias[c + 1]);
                    v0 += bc0; v1 += bc1; v2 += bc0; v3 += bc1;
                }
                float* Cg = Cf + cOff;
                *(float2*)&Cg[(size_t)r * ldC + c]       = make_float2(v0, v1);
                *(float2*)&Cg[(size_t)(r + 8) * ldC + c] = make_float2(v2, v3);
            } else {
                __half* Cb = Cbh + cOff;
                __half* Cs = Csh + cOff;
                uint32_t b0, s0, b1, s1;
                splitf(v0, v1, b0, s0);
                splitf(v2, v3, b1, s1);
                *(uint32_t*)&Cb[(size_t)r * ldC + c]       = b0;
                *(uint32_t*)&Cs[(size_t)r * ldC + c]       = s0;
                *(uint32_t*)&Cb[(size_t)(r + 8) * ldC + c] = b1;
                *(uint32_t*)&Cs[(size_t)(r + 8) * ldC + c] = s1;
            }
        }
    }
}

// ==========================================================================
// split-K reduce + bias -> split halves
// ==========================================================================
__global__ void reduce_split(const float* __restrict__ part, const float* __restrict__ bias,
                             __half* __restrict__ ob, __half* __restrict__ os,
                             int cols, int biasCol)
{
    const int per = (K_ * HD_) / 4;
    const int i = blockIdx.x * 256 + threadIdx.x;
    const int b = blockIdx.y;
    const float4* p = (const float4*)part + (size_t)b * 4 * per;
    float4 v = p[i];
    float4 v1 = p[per + i], v2 = p[2 * per + i], v3 = p[3 * per + i];
    v.x += v1.x + v2.x + v3.x; v.y += v1.y + v2.y + v3.y;
    v.z += v1.z + v2.z + v3.z; v.w += v1.w + v2.w + v3.w;
    const int e = i * 4;
    if (biasCol) {
        const int c = e % cols;
        v.x += bias[c]; v.y += bias[c + 1]; v.z += bias[c + 2]; v.w += bias[c + 3];
    } else {
        const float bb = bias[e / cols];
        v.x += bb; v.y += bb; v.z += bb; v.w += bb;
    }
    uint32_t b0, s0, b1, s1;
    splitf(v.x, v.y, b0, s0);
    splitf(v.z, v.w, b1, s1);
    ((uint2*)ob)[(size_t)b * per + i] = make_uint2(b0, b1);
    ((uint2*)os)[(size_t)b * per + i] = make_uint2(s0, s1);
}

// ==========================================================================
// Fused attention: CTA = (128 rows, head h, batch b), 8 warps
// ==========================================================================
#define QSTR 72
#define VSTR 264
#define OQB 0
#define OQS (128 * QSTR)
#define OKB (2 * 128 * QSTR)
#define OKS (OKB + 256 * QSTR)
#define OVB (OKS + 256 * QSTR)
#define OVS (OVB + 64 * VSTR)
#define ATT_SMEM ((OVS + 64 * VSTR) * 2)

__global__ void __launch_bounds__(256, 1)
attn_mma(const __half* __restrict__ Qb, const __half* __restrict__ Qs,
         const __half* __restrict__ KEb, const __half* __restrict__ KEs,
         const __half* __restrict__ VFb, const __half* __restrict__ VFs,
         __half* __restrict__ Ob, __half* __restrict__ Os)
{
    extern __shared__ __half sh[];
    const int tid = threadIdx.x, wid = tid >> 5, lane = tid & 31;
    const int b = blockIdx.z, h = blockIdx.y, n0 = blockIdx.x * 128;
    const uint32_t shb = su32(sh);

    const __half* Qgb = Qb  + ((size_t)(b * N_ + n0)) * HD_ + h * D_;
    const __half* Qgs = Qs  + ((size_t)(b * N_ + n0)) * HD_ + h * D_;
    const __half* Kgb = KEb + ((size_t)b * K_) * HD_ + h * D_;
    const __half* Kgs = KEs + ((size_t)b * K_) * HD_ + h * D_;
    const __half* Vgb = VFb + ((size_t)(b * HD_ + h * D_)) * K_;
    const __half* Vgs = VFs + ((size_t)(b * HD_ + h * D_)) * K_;

#pragma unroll
    for (int p = 0; p < 4; p++) {         // Q: 128 rows x 8 chunks
        const int id = p * 256 + tid;
        const int r = id >> 3, c = id & 7;
        const size_t g = (size_t)r * HD_ + c * 8;
        const uint32_t d = (r * QSTR + c * 8) * 2;
        CP16(shb + OQB * 2 + d, Qgb + g);
        CP16(shb + OQS * 2 + d, Qgs + g);
    }
#pragma unroll
    for (int p = 0; p < 8; p++) {         // KE: 256 rows x 8 chunks
        const int id = p * 256 + tid;
        const int r = id >> 3, c = id & 7;
        const size_t g = (size_t)r * HD_ + c * 8;
        const uint32_t d = (r * QSTR + c * 8) * 2;
        CP16(shb + OKB * 2 + d, Kgb + g);
        CP16(shb + OKS * 2 + d, Kgs + g);
    }
#pragma unroll
    for (int p = 0; p < 8; p++) {         // VF: 64 rows x 32 chunks
        const int id = p * 256 + tid;
        const int r = id >> 5, c = id & 31;
        const size_t g = (size_t)r * K_ + c * 8;
        const uint32_t d = (r * VSTR + c * 8) * 2;
        CP16(shb + OVB * 2 + d, Vgb + g);
        CP16(shb + OVS * 2 + d, Vgs + g);
    }
    CPCOMMIT();
    CPWAIT(0);
    __syncthreads();

    // ---- scores
    float sacc[32][4];
#pragma unroll
    for (int j = 0; j < 32; j++)
#pragma unroll
        for (int q = 0; q < 4; q++) sacc[j][q] = 0.f;

    const int r0 = wid * 16;
    const uint32_t aoff = ((r0 + (lane & 15)) * QSTR + 8 * (lane >> 4)) * 2;
    const uint32_t boff = (((lane & 7) + 8 * (lane >> 4)) * QSTR + 8 * ((lane >> 3) & 1)) * 2;

#pragma unroll
    for (int ks = 0; ks < 64; ks += 16) {
        uint32_t ab[4], as_[4];
        LDM4(ab,  shb + OQB * 2 + aoff + ks * 2);
        LDM4(as_, shb + OQS * 2 + aoff + ks * 2);
#pragma unroll
        for (int np = 0; np < 16; np++) {
            uint32_t kb[4], ksm[4];
            const uint32_t bd = boff + (np * 16 * QSTR + ks) * 2;
            LDM4(kb,  shb + OKB * 2 + bd);
            LDM4(ksm, shb + OKS * 2 + bd);
            mma16816(sacc[2 * np],     ab,  kb);
            mma16816(sacc[2 * np],     ab,  ksm);
            mma16816(sacc[2 * np],     as_, kb);
            mma16816(sacc[2 * np + 1], ab,  kb + 2);
            mma16816(sacc[2 * np + 1], ab,  ksm + 2);
            mma16816(sacc[2 * np + 1], as_, kb + 2);
        }
    }

    // ---- softmax
    float mx0 = -1e30f, mx1 = -1e30f;
#pragma unroll
    for (int j = 0; j < 32; j++) {
        mx0 = fmaxf(mx0, fmaxf(sacc[j][0], sacc[j][1]));
        mx1 = fmaxf(mx1, fmaxf(sacc[j][2], sacc[j][3]));
    }
    mx0 = fmaxf(mx0, __shfl_xor_sync(0xffffffffu, mx0, 1));
    mx0 = fmaxf(mx0, __shfl_xor_sync(0xffffffffu, mx0, 2));
    mx1 = fmaxf(mx1, __shfl_xor_sync(0xffffffffu, mx1, 1));
    mx1 = fmaxf(mx1, __shfl_xor_sync(0xffffffffu, mx1, 2));
    float sum0 = 0.f, sum1 = 0.f;
#pragma unroll
    for (int j = 0; j < 32; j++) {
        float e0 = __expf((sacc[j][0] - mx0) * 0.125f);
        float e1 = __expf((sacc[j][1] - mx0) * 0.125f);
        float e2 = __expf((sacc[j][2] - mx1) * 0.125f);
        float e3 = __expf((sacc[j][3] - mx1) * 0.125f);
        sacc[j][0] = e0; sacc[j][1] = e1; sacc[j][2] = e2; sacc[j][3] = e3;
        sum0 += e0 + e1; sum1 += e2 + e3;
    }
    sum0 += __shfl_xor_sync(0xffffffffu, sum0, 1);
    sum0 += __shfl_xor_sync(0xffffffffu, sum0, 2);
    sum1 += __shfl_xor_sync(0xffffffffu, sum1, 1);
    sum1 += __shfl_xor_sync(0xffffffffu, sum1, 2);
    const float inv0 = 1.0f / sum0, inv1 = 1.0f / sum1;
#pragma unroll
    for (int j = 0; j < 32; j++) {
        sacc[j][0] *= inv0; sacc[j][1] *= inv0;
        sacc[j][2] *= inv1; sacc[j][3] *= inv1;
    }

    // ---- PV
    float oacc[8][4];
#pragma unroll
    for (int n = 0; n < 8; n++)
#pragma unroll
        for (int q = 0; q < 4; q++) oacc[n][q] = 0.f;

#pragma unroll
    for (int kt = 0; kt < 16; kt++) {
        uint32_t pa[4], ps[4];
        splitf(sacc[2 * kt][0],     sacc[2 * kt][1],     pa[0], ps[0]);
        splitf(sacc[2 * kt][2],     sacc[2 * kt][3],     pa[1], ps[1]);
        splitf(sacc[2 * kt + 1][0], sacc[2 * kt + 1][1], pa[2], ps[2]);
        splitf(sacc[2 * kt + 1][2], sacc[2 * kt + 1][3], pa[3], ps[3]);
#pragma unroll
        for (int np = 0; np < 4; np++) {
            const uint32_t bd = (((lane & 7) + 8 * (lane >> 4) + np * 16) * VSTR
                                 + kt * 16 + 8 * ((lane >> 3) & 1)) * 2;
            uint32_t vb[4], vs[4];
            LDM4(vb, shb + OVB * 2 + bd);
            LDM4(vs, shb + OVS * 2 + bd);
            mma16816(oacc[2 * np],     pa, vb);
            mma16816(oacc[2 * np],     pa, vs);
            mma16816(oacc[2 * np],     ps, vb);
            mma16816(oacc[2 * np + 1], pa, vb + 2);
            mma16816(oacc[2 * np + 1], pa, vs + 2);
            mma16816(oacc[2 * np + 1], ps, vb + 2);
        }
    }

    // ---- store O as split halves
    const int orow = n0 + r0 + (lane >> 2);
    const int ocol = h * D_ + 2 * (lane & 3);
    __half* Obp = Ob + ((size_t)b * N_) * HD_;
    __half* Osp = Os + ((size_t)b * N_) * HD_;
#pragma unroll
    for (int n = 0; n < 8; n++) {
        uint32_t b0, s0, b1, s1;
        splitf(oacc[n][0], oacc[n][1], b0, s0);
        splitf(oacc[n][2], oacc[n][3], b1, s1);
        *(uint32_t*)&Obp[(size_t)orow * HD_ + ocol + n * 8]       = b0;
        *(uint32_t*)&Osp[(size_t)orow * HD_ + ocol + n * 8]       = s0;
        *(uint32_t*)&Obp[(size_t)(orow + 8) * HD_ + ocol + n * 8] = b1;
        *(uint32_t*)&Osp[(size_t)(orow + 8) * HD_ + ocol + n * 8] = s1;
    }
}

// ==========================================================================
extern "C" void kernel_launch(void* const* d_in, const int* in_sizes, int n_in,
                              void* d_out, int out_size)
{
    const float* X  = (const float*)d_in[0];
    const float* Wq = (const float*)d_in[1];
    const float* Wk = (const float*)d_in[2];
    const float* Wv = (const float*)d_in[3];
    const float* We = (const float*)d_in[4];
    const float* be = (const float*)d_in[5];
    const float* Wf = (const float*)d_in[6];
    const float* bf = (const float*)d_in[7];
    const float* Wo = (const float*)d_in[8];
    const float* bo = (const float*)d_in[9];
    float* out = (float*)d_out;

    __half *Xb, *Xs, *Wqb, *Wqs, *Wkb, *Wks, *Wvb, *Wvs, *Web, *Wes, *Wfb, *Wfs, *Wob, *Wos;
    __half *Qb, *Qs, *Ktb, *Kts, *Vtb, *Vts, *KEbp, *KEsp, *VFbp, *VFsp, *Obp, *Osp;
    float* Pp;
    cudaGetSymbolAddress((void**)&Xb,  h_Xb);  cudaGetSymbolAddress((void**)&Xs,  h_Xs);
    cudaGetSymbolAddress((void**)&Wqb, h_Wqb); cudaGetSymbolAddress((void**)&Wqs, h_Wqs);
    cudaGetSymbolAddress((void**)&Wkb, h_Wkb); cudaGetSymbolAddress((void**)&Wks, h_Wks);
    cudaGetSymbolAddress((void**)&Wvb, h_Wvb); cudaGetSymbolAddress((void**)&Wvs, h_Wvs);
    cudaGetSymbolAddress((void**)&Web, h_Web); cudaGetSymbolAddress((void**)&Wes, h_Wes);
    cudaGetSymbolAddress((void**)&Wfb, h_Wfb); cudaGetSymbolAddress((void**)&Wfs, h_Wfs);
    cudaGetSymbolAddress((void**)&Wob, h_Wob); cudaGetSymbolAddress((void**)&Wos, h_Wos);
    cudaGetSymbolAddress((void**)&Qb,  h_Qb);  cudaGetSymbolAddress((void**)&Qs,  h_Qs);
    cudaGetSymbolAddress((void**)&Ktb, h_Ktb); cudaGetSymbolAddress((void**)&Kts, h_Kts);
    cudaGetSymbolAddress((void**)&Vtb, h_Vtb); cudaGetSymbolAddress((void**)&Vts, h_Vts);
    cudaGetSymbolAddress((void**)&KEbp, h_KEb); cudaGetSymbolAddress((void**)&KEsp, h_KEs);
    cudaGetSymbolAddress((void**)&VFbp, h_VFb); cudaGetSymbolAddress((void**)&VFsp, h_VFs);
    cudaGetSymbolAddress((void**)&Obp, h_Ob);  cudaGetSymbolAddress((void**)&Osp, h_Os);
    cudaGetSymbolAddress((void**)&Pp,  g_part);

    cudaFuncSetAttribute(hgemm<0, 0>, cudaFuncAttributeMaxDynamicSharedMemorySize, GEMM_SMEM);
    cudaFuncSetAttribute(hgemm<0, 1>, cudaFuncAttributeMaxDynamicSharedMemorySize, GEMM_SMEM);
    cudaFuncSetAttribute(hgemm<1, 0>, cudaFuncAttributeMaxDynamicSharedMemorySize, GEMM_SMEM);
    cudaFuncSetAttribute(attn_mma, cudaFuncAttributeMaxDynamicSharedMemorySize, ATT_SMEM);

    // ---- pre-split inputs (2 launches: X, then all six 1M-element weights)
    split_arr<<<M_ * C_ / 4 / 256, 256>>>(X, Xb, Xs, M_ * C_ / 4);
    split6<<<dim3(HD_ * C_ / 4 / 256, 6), 256>>>(
        Wq, Wqb, Wqs, Wk, Wkb, Wks, Wv, Wvb, Wvs,
        We, Web, Wes, Wf, Wfb, Wfs, Wo, Wob, Wos);

    // ---- Q = X * Wq^T -> split halves           [8192, 1024]
    hgemm<1, 0><<<dim3(8, 64, 1), 256, GEMM_SMEM>>>(Xb, Xs, Wqb, Wqs, nullptr,
        nullptr, Qb, Qs, 1024, 1024, 1024, 1024, 0, 0, 0, 0);
    // ---- Kt[b] = Wk * X_b^T -> halves           [1024, 4096] per b
    hgemm<1, 0><<<dim3(32, 8, B_), 256, GEMM_SMEM>>>(Wkb, Wks, Xb, Xs, nullptr,
        nullptr, Ktb, Kts, 1024, 1024, 4096, 1024, 0, (long)N_ * C_, (long)HD_ * N_, 0);
    // ---- Vt[b] = Wv * X_b^T -> halves
    hgemm<1, 0><<<dim3(32, 8, B_), 256, GEMM_SMEM>>>(Wvb, Wvs, Xb, Xs, nullptr,
        nullptr, Vtb, Vts, 1024, 1024, 4096, 1024, 0, (long)N_ * C_, (long)HD_ * N_, 0);
    // ---- KE partials (split-K x4): We * Kt^T -> fp32   [256, 1024]
    hgemm<0, 0><<<dim3(8, 2, 8), 256, GEMM_SMEM>>>(Web, Wes, Ktb, Kts, nullptr,
        Pp, nullptr, nullptr, 4096, 4096, 1024, 1024, 0, (long)HD_ * N_, (long)K_ * HD_, 1);
    reduce_split<<<dim3((K_ * HD_ / 4) / 256, B_), 256>>>(Pp, be, KEbp, KEsp, HD_, 0);
    // ---- VFt partials (split-K x4): Vt * Wf^T -> fp32  [1024, 256]
    hgemm<0, 0><<<dim3(2, 8, 8), 256, GEMM_SMEM>>>(Vtb, Vts, Wfb, Wfs, nullptr,
        Pp, nullptr, nullptr, 4096, 4096, 256, 1024, (long)HD_ * N_, 0, (long)HD_ * K_, 1);
    reduce_split<<<dim3((HD_ * K_ / 4) / 256, B_), 256>>>(Pp, bf, VFbp, VFsp, K_, 1);
    // ---- fused attention -> O halves
    attn_mma<<<dim3(N_ / 128, H_, B_), 256, ATT_SMEM>>>(Qb, Qs, KEbp, KEsp, VFbp, VFsp, Obp, Osp);
    // ---- out = O * Wo^T + bo                     [8192, 1024] fp32
    hgemm<0, 1><<<dim3(8, 64, 1), 256, GEMM_SMEM>>>(Obp, Osp, Wob, Wos, bo,
        out, nullptr, nullptr, 1024, 1024, 1024, 1024, 0, 0, 0, 0);
}

// round 9
// speedup vs baseline: 1.5484x; 1.3896x over previous
#include <cuda_runtime.h>
#include <cuda_fp16.h>
#include <cstdint>

#define B_  2
#define N_  4096
#define C_  1024
#define H_  16
#define D_  64
#define K_  256
#define HD_ 1024
#define M_  8192

// ---------------- persistent split (big/small) fp16 buffers -------------
__device__ __half h_Xb [M_ * C_],    h_Xs [M_ * C_];
__device__ __half h_Wqb[HD_ * C_],   h_Wqs[HD_ * C_];
__device__ __half h_Wkb[HD_ * C_],   h_Wks[HD_ * C_];
__device__ __half h_Wvb[HD_ * C_],   h_Wvs[HD_ * C_];
__device__ __half h_Web[K_ * N_],    h_Wes[K_ * N_];
__device__ __half h_Wfb[K_ * N_],    h_Wfs[K_ * N_];
__device__ __half h_Wob[C_ * HD_],   h_Wos[C_ * HD_];
__device__ __half h_Qb [M_ * HD_],   h_Qs [M_ * HD_];
__device__ __half h_Ktb[B_ * HD_ * N_], h_Kts[B_ * HD_ * N_];
__device__ __half h_Vtb[B_ * HD_ * N_], h_Vts[B_ * HD_ * N_];
__device__ __half h_KEb[B_ * K_ * HD_], h_KEs[B_ * K_ * HD_];
__device__ __half h_VFb[B_ * HD_ * K_], h_VFs[B_ * HD_ * K_];
__device__ __half h_Ob [M_ * HD_];
__device__ float  g_part[8 * K_ * HD_];

#define DEV __device__ __forceinline__

DEV uint32_t su32(const void* p) {
    uint32_t a;
    asm("{ .reg .u64 t; cvta.to.shared.u64 t, %1; cvt.u32.u64 %0, t; }" : "=r"(a) : "l"(p));
    return a;
}
DEV void splitf(float x, float y, uint32_t& bo, uint32_t& so) {
    __half hx = __float2half_rn(x), hy = __float2half_rn(y);
    __half2 hb = __halves2half2(hx, hy);
    bo = *(uint32_t*)&hb;
    __half2 hs = __floats2half2_rn(x - __half2float(hx), y - __half2float(hy));
    so = *(uint32_t*)&hs;
}
DEV uint32_t packh2(float x, float y) {
    __half2 h = __floats2half2_rn(x, y);
    return *(uint32_t*)&h;
}

#define CP16(dst, src) asm volatile("cp.async.cg.shared.global [%0], [%1], 16;" :: "r"(dst), "l"(src) : "memory")
#define CPCOMMIT() asm volatile("cp.async.commit_group;" ::: "memory")
#define CPWAIT(n)  asm volatile("cp.async.wait_group %0;" :: "n"(n) : "memory")

#define LDM4(r, a) \
    asm volatile("ldmatrix.sync.aligned.m8n8.x4.shared.b16 {%0,%1,%2,%3}, [%4];" \
        : "=r"((r)[0]), "=r"((r)[1]), "=r"((r)[2]), "=r"((r)[3]) : "r"(a))

DEV void mma16816(float* d, const uint32_t* a, const uint32_t* b) {
    asm volatile("mma.sync.aligned.m16n8k16.row.col.f32.f16.f16.f32 "
        "{%0,%1,%2,%3}, {%4,%5,%6,%7}, {%8,%9}, {%0,%1,%2,%3};"
        : "+f"(d[0]), "+f"(d[1]), "+f"(d[2]), "+f"(d[3])
        : "r"(a[0]), "r"(a[1]), "r"(a[2]), "r"(a[3]), "r"(b[0]), "r"(b[1]));
}

// swizzled byte offset inside a 128x32-half tile (rows of 64B, 16B chunks)
DEV uint32_t tswz(int r, int ch) { return (r << 6) | (((ch ^ ((r >> 1) & 3)) & 3) << 4); }

// ==========================================================================
// split passes: fp32 -> (big, small) fp16
// ==========================================================================
__global__ void split_arr(const float* __restrict__ in, __half* __restrict__ ob,
                          __half* __restrict__ os, int n4)
{
    const int i = blockIdx.x * 256 + threadIdx.x;
    if (i >= n4) return;
    float4 v = ((const float4*)in)[i];
    uint32_t b0, s0, b1, s1;
    splitf(v.x, v.y, b0, s0);
    splitf(v.z, v.w, b1, s1);
    ((uint2*)ob)[i] = make_uint2(b0, b1);
    ((uint2*)os)[i] = make_uint2(s0, s1);
}

// six equal-size (1M element) weight arrays in one launch; grid.y selects
__global__ void split6(const float* w0, __half* b0, __half* s0,
                       const float* w1, __half* b1, __half* s1,
                       const float* w2, __half* b2, __half* s2,
                       const float* w3, __half* b3, __half* s3,
                       const float* w4, __half* b4, __half* s4,
                       const float* w5, __half* b5, __half* s5)
{
    const int y = blockIdx.y;
    const float* in = (y == 0) ? w0 : (y == 1) ? w1 : (y == 2) ? w2
                    : (y == 3) ? w3 : (y == 4) ? w4 : w5;
    __half* ob = (y == 0) ? b0 : (y == 1) ? b1 : (y == 2) ? b2
               : (y == 3) ? b3 : (y == 4) ? b4 : b5;
    __half* os = (y == 0) ? s0 : (y == 1) ? s1 : (y == 2) ? s2
               : (y == 3) ? s3 : (y == 4) ? s4 : s5;
    const int i = blockIdx.x * 256 + threadIdx.x;
    float4 v = ((const float4*)in)[i];
    uint32_t c0, d0, c1, d1;
    splitf(v.x, v.y, c0, d0);
    splitf(v.z, v.w, c1, d1);
    ((uint2*)ob)[i] = make_uint2(c0, c1);
    ((uint2*)os)[i] = make_uint2(d0, d1);
}

// ==========================================================================
// fp16 2-term GEMM: C[M,N] = Ab[M,K] * (Bb+Bs)[N,K]^T
// 128x128 tile, BK=32, 256 thr, warp tile 64x32, cp.async 3-stage, swizzled
// 2 CTAs/SM resident. EPI: 0 = fp32 out (+opt col bias), 1 = split-half out
// ==========================================================================
#define GEMM_SMEM 73728   // 3 stages x 24 KB

template<int EPI, int BIASCOL>
__global__ void __launch_bounds__(256, 2)
hgemm(const __half* __restrict__ Ab_,
      const __half* __restrict__ Bb_, const __half* __restrict__ Bs_,
      const float* __restrict__ bias, float* __restrict__ Cf,
      __half* __restrict__ Cbh, __half* __restrict__ Csh,
      int ldA, int ldB, int ldC, int Kdim,
      long zA, long zB, long zC, int splitk)
{
    extern __shared__ __half sh[];
    const int tid = threadIdx.x, wid = tid >> 5, lane = tid & 31;
    const uint32_t shb = su32(sh);

    long aOff, bOff, cOff;
    if (splitk) {
        int zb = blockIdx.z >> 2, ks = blockIdx.z & 3;
        aOff = (long)zb * zA + ks * 1024;
        bOff = (long)zb * zB + ks * 1024;
        cOff = (long)blockIdx.z * zC;
    } else {
        aOff = (long)blockIdx.z * zA;
        bOff = (long)blockIdx.z * zB;
        cOff = (long)blockIdx.z * zC;
    }
    const __half* Agb = Ab_ + aOff + (size_t)(blockIdx.y * 128) * ldA;
    const __half* Bgb = Bb_ + bOff + (size_t)(blockIdx.x * 128) * ldB;
    const __half* Bgs = Bs_ + bOff + (size_t)(blockIdx.x * 128) * ldB;

    const int wm = (wid >> 2) * 64, wn = (wid & 3) * 32;

    float acc[4][4][4];
#pragma unroll
    for (int m = 0; m < 4; m++)
#pragma unroll
        for (int n = 0; n < 4; n++)
#pragma unroll
            for (int j = 0; j < 4; j++) acc[m][n][j] = 0.f;

    // stage layout (bytes): Ab@0, Bb@8192, Bs@16384; stage stride 24576
    auto PREFETCH = [&](int kt, int s) {
        const uint32_t st = shb + s * 24576;
        const int kc = kt * 32;
#pragma unroll
        for (int p = 0; p < 2; p++) {
            const int id = p * 256 + tid;
            const int r = id >> 2, c = id & 3;
            const uint32_t d = st + tswz(r, c);
            const size_t ga = (size_t)r * ldA + kc + c * 8;
            const size_t gb = (size_t)r * ldB + kc + c * 8;
            CP16(d,         Agb + ga);
            CP16(d +  8192, Bgb + gb);
            CP16(d + 16384, Bgs + gb);
        }
    };

    auto COMPUTE = [&](int s) {
        const uint32_t base = shb + s * 24576;
#pragma unroll
        for (int ks2 = 0; ks2 < 2; ks2++) {
            uint32_t ab[4][4];
#pragma unroll
            for (int m = 0; m < 4; m++) {
                const int r = wm + m * 16 + (lane & 15);
                const int ch = ks2 * 2 + (lane >> 4);
                LDM4(ab[m], base + tswz(r, ch));
            }
#pragma unroll
            for (int np = 0; np < 2; np++) {
                const int r = wn + np * 16 + (lane & 7) + 8 * (lane >> 4);
                const int ch = ks2 * 2 + ((lane >> 3) & 1);
                const uint32_t bd = base + 8192 + tswz(r, ch);
                uint32_t bb[4], bs[4];
                LDM4(bb, bd);
                LDM4(bs, bd + 8192);
#pragma unroll
                for (int m = 0; m < 4; m++) {
                    mma16816(acc[m][2 * np],     ab[m], bb);
                    mma16816(acc[m][2 * np],     ab[m], bs);
                    mma16816(acc[m][2 * np + 1], ab[m], bb + 2);
                    mma16816(acc[m][2 * np + 1], ab[m], bs + 2);
                }
            }
        }
    };

    const int NK = Kdim >> 5;
    PREFETCH(0, 0); CPCOMMIT();
    PREFETCH(1, 1); CPCOMMIT();
    int sc = 0, sp = 2;
    for (int kt = 0; kt < NK; kt++) {
        if (kt + 2 < NK) CPWAIT(1); else CPWAIT(0);
        __syncthreads();
        if (kt + 2 < NK) { PREFETCH(kt + 2, sp); CPCOMMIT(); }
        COMPUTE(sc);
        sc = (sc == 2) ? 0 : sc + 1;
        sp = (sp == 2) ? 0 : sp + 1;
    }

    const int row0 = blockIdx.y * 128 + wm + (lane >> 2);
    const int col0 = blockIdx.x * 128 + wn + 2 * (lane & 3);
#pragma unroll
    for (int m = 0; m < 4; m++) {
#pragma unroll
        for (int n = 0; n < 4; n++) {
            const int r = row0 + m * 16, c = col0 + n * 8;
            float v0 = acc[m][n][0], v1 = acc[m][n][1];
            float v2 = acc[m][n][2], v3 = acc[m][n][3];
            if (EPI == 0) {
                if (BIASCOL) {
                    const float bc0 = __ldg(&bias[c]), bc1 = __ldg(&bias[c + 1]);
                    v0 += bc0; v1 += bc1; v2 += bc0; v3 += bc1;
                }
                float* Cg = Cf + cOff;
                *(float2*)&Cg[(size_t)r * ldC + c]       = make_float2(v0, v1);
                *(float2*)&Cg[(size_t)(r + 8) * ldC + c] = make_float2(v2, v3);
            } else {
                __half* Cb = Cbh + cOff;
                __half* Cs = Csh + cOff;
                uint32_t b0, s0, b1, s1;
                splitf(v0, v1, b0, s0);
                splitf(v2, v3, b1, s1);
                *(uint32_t*)&Cb[(size_t)r * ldC + c]       = b0;
                *(uint32_t*)&Cs[(size_t)r * ldC + c]       = s0;
                *(uint32_t*)&Cb[(size_t)(r + 8) * ldC + c] = b1;
                *(uint32_t*)&Cs[(size_t)(r + 8) * ldC + c] = s1;
            }
        }
    }
}

// ==========================================================================
// split-K reduce + bias -> split halves
// ==========================================================================
__global__ void reduce_split(const float* __restrict__ part, const float* __restrict__ bias,
                             __half* __restrict__ ob, __half* __restrict__ os,
                             int cols, int biasCol)
{
    const int per = (K_ * HD_) / 4;
    const int i = blockIdx.x * 256 + threadIdx.x;
    const int b = blockIdx.y;
    const float4* p = (const float4*)part + (size_t)b * 4 * per;
    float4 v = p[i];
    float4 v1 = p[per + i], v2 = p[2 * per + i], v3 = p[3 * per + i];
    v.x += v1.x + v2.x + v3.x; v.y += v1.y + v2.y + v3.y;
    v.z += v1.z + v2.z + v3.z; v.w += v1.w + v2.w + v3.w;
    const int e = i * 4;
    if (biasCol) {
        const int c = e % cols;
        v.x += bias[c]; v.y += bias[c + 1]; v.z += bias[c + 2]; v.w += bias[c + 3];
    } else {
        const float bb = bias[e / cols];
        v.x += bb; v.y += bb; v.z += bb; v.w += bb;
    }
    uint32_t b0, s0, b1, s1;
    splitf(v.x, v.y, b0, s0);
    splitf(v.z, v.w, b1, s1);
    ((uint2*)ob)[(size_t)b * per + i] = make_uint2(b0, b1);
    ((uint2*)os)[(size_t)b * per + i] = make_uint2(s0, s1);
}

// ==========================================================================
// Fused attention: CTA = (128 rows, head h, batch b), 8 warps
// scores = Qb * (KEb+KEs)^T; softmax; O = P16 * (VFb+VFs)^T; store O fp16
// ==========================================================================
#define QSTR 72
#define VSTR 264
#define OQB 0
#define OKB (128 * QSTR)
#define OKS (OKB + 256 * QSTR)
#define OVB (OKS + 256 * QSTR)
#define OVS (OVB + 64 * VSTR)
#define ATT_SMEM ((OVS + 64 * VSTR) * 2)   // 159744 bytes

__global__ void __launch_bounds__(256, 1)
attn_mma(const __half* __restrict__ Qb, const __half* __restrict__ KEb,
         const __half* __restrict__ KEs, const __half* __restrict__ VFb,
         const __half* __restrict__ VFs, __half* __restrict__ Ob)
{
    extern __shared__ __half sh[];
    const int tid = threadIdx.x, wid = tid >> 5, lane = tid & 31;
    const int b = blockIdx.z, h = blockIdx.y, n0 = blockIdx.x * 128;
    const uint32_t shb = su32(sh);

    const __half* Qgb = Qb  + ((size_t)(b * N_ + n0)) * HD_ + h * D_;
    const __half* Kgb = KEb + ((size_t)b * K_) * HD_ + h * D_;
    const __half* Kgs = KEs + ((size_t)b * K_) * HD_ + h * D_;
    const __half* Vgb = VFb + ((size_t)(b * HD_ + h * D_)) * K_;
    const __half* Vgs = VFs + ((size_t)(b * HD_ + h * D_)) * K_;

#pragma unroll
    for (int p = 0; p < 4; p++) {         // Q: 128 rows x 8 chunks (big only)
        const int id = p * 256 + tid;
        const int r = id >> 3, c = id & 7;
        CP16(shb + OQB * 2 + (r * QSTR + c * 8) * 2, Qgb + (size_t)r * HD_ + c * 8);
    }
#pragma unroll
    for (int p = 0; p < 8; p++) {         // KE: 256 rows x 8 chunks
        const int id = p * 256 + tid;
        const int r = id >> 3, c = id & 7;
        const size_t g = (size_t)r * HD_ + c * 8;
        const uint32_t d = (r * QSTR + c * 8) * 2;
        CP16(shb + OKB * 2 + d, Kgb + g);
        CP16(shb + OKS * 2 + d, Kgs + g);
    }
#pragma unroll
    for (int p = 0; p < 8; p++) {         // VF: 64 rows x 32 chunks
        const int id = p * 256 + tid;
        const int r = id >> 5, c = id & 31;
        const size_t g = (size_t)r * K_ + c * 8;
        const uint32_t d = (r * VSTR + c * 8) * 2;
        CP16(shb + OVB * 2 + d, Vgb + g);
        CP16(shb + OVS * 2 + d, Vgs + g);
    }
    CPCOMMIT();
    CPWAIT(0);
    __syncthreads();

    // ---- scores
    float sacc[32][4];
#pragma unroll
    for (int j = 0; j < 32; j++)
#pragma unroll
        for (int q = 0; q < 4; q++) sacc[j][q] = 0.f;

    const int r0 = wid * 16;
    const uint32_t aoff = ((r0 + (lane & 15)) * QSTR + 8 * (lane >> 4)) * 2;
    const uint32_t boff = (((lane & 7) + 8 * (lane >> 4)) * QSTR + 8 * ((lane >> 3) & 1)) * 2;

#pragma unroll
    for (int ks = 0; ks < 64; ks += 16) {
        uint32_t ab[4];
        LDM4(ab, shb + OQB * 2 + aoff + ks * 2);
#pragma unroll
        for (int np = 0; np < 16; np++) {
            uint32_t kb[4], ksm[4];
            const uint32_t bd = boff + (np * 16 * QSTR + ks) * 2;
            LDM4(kb,  shb + OKB * 2 + bd);
            LDM4(ksm, shb + OKS * 2 + bd);
            mma16816(sacc[2 * np],     ab, kb);
            mma16816(sacc[2 * np],     ab, ksm);
            mma16816(sacc[2 * np + 1], ab, kb + 2);
            mma16816(sacc[2 * np + 1], ab, ksm + 2);
        }
    }

    // ---- softmax
    float mx0 = -1e30f, mx1 = -1e30f;
#pragma unroll
    for (int j = 0; j < 32; j++) {
        mx0 = fmaxf(mx0, fmaxf(sacc[j][0], sacc[j][1]));
        mx1 = fmaxf(mx1, fmaxf(sacc[j][2], sacc[j][3]));
    }
    mx0 = fmaxf(mx0, __shfl_xor_sync(0xffffffffu, mx0, 1));
    mx0 = fmaxf(mx0, __shfl_xor_sync(0xffffffffu, mx0, 2));
    mx1 = fmaxf(mx1, __shfl_xor_sync(0xffffffffu, mx1, 1));
    mx1 = fmaxf(mx1, __shfl_xor_sync(0xffffffffu, mx1, 2));
    float sum0 = 0.f, sum1 = 0.f;
#pragma unroll
    for (int j = 0; j < 32; j++) {
        float e0 = __expf((sacc[j][0] - mx0) * 0.125f);
        float e1 = __expf((sacc[j][1] - mx0) * 0.125f);
        float e2 = __expf((sacc[j][2] - mx1) * 0.125f);
        float e3 = __expf((sacc[j][3] - mx1) * 0.125f);
        sacc[j][0] = e0; sacc[j][1] = e1; sacc[j][2] = e2; sacc[j][3] = e3;
        sum0 += e0 + e1; sum1 += e2 + e3;
    }
    sum0 += __shfl_xor_sync(0xffffffffu, sum0, 1);
    sum0 += __shfl_xor_sync(0xffffffffu, sum0, 2);
    sum1 += __shfl_xor_sync(0xffffffffu, sum1, 1);
    sum1 += __shfl_xor_sync(0xffffffffu, sum1, 2);
    const float inv0 = 1.0f / sum0, inv1 = 1.0f / sum1;
#pragma unroll
    for (int j = 0; j < 32; j++) {
        sacc[j][0] *= inv0; sacc[j][1] *= inv0;
        sacc[j][2] *= inv1; sacc[j][3] *= inv1;
    }

    // ---- PV (P as plain fp16)
    float oacc[8][4];
#pragma unroll
    for (int n = 0; n < 8; n++)
#pragma unroll
        for (int q = 0; q < 4; q++) oacc[n][q] = 0.f;

#pragma unroll
    for (int kt = 0; kt < 16; kt++) {
        uint32_t pa[4];
        pa[0] = packh2(sacc[2 * kt][0],     sacc[2 * kt][1]);
        pa[1] = packh2(sacc[2 * kt][2],     sacc[2 * kt][3]);
        pa[2] = packh2(sacc[2 * kt + 1][0], sacc[2 * kt + 1][1]);
        pa[3] = packh2(sacc[2 * kt + 1][2], sacc[2 * kt + 1][3]);
#pragma unroll
        for (int np = 0; np < 4; np++) {
            const uint32_t bd = (((lane & 7) + 8 * (lane >> 4) + np * 16) * VSTR
                                 + kt * 16 + 8 * ((lane >> 3) & 1)) * 2;
            uint32_t vb[4], vs[4];
            LDM4(vb, shb + OVB * 2 + bd);
            LDM4(vs, shb + OVS * 2 + bd);
            mma16816(oacc[2 * np],     pa, vb);
            mma16816(oacc[2 * np],     pa, vs);
            mma16816(oacc[2 * np + 1], pa, vb + 2);
            mma16816(oacc[2 * np + 1], pa, vs + 2);
        }
    }

    // ---- store O (fp16 big only; out-proj uses A = Ob)
    const int orow = n0 + r0 + (lane >> 2);
    const int ocol = h * D_ + 2 * (lane & 3);
    __half* Obp = Ob + ((size_t)b * N_) * HD_;
#pragma unroll
    for (int n = 0; n < 8; n++) {
        *(uint32_t*)&Obp[(size_t)orow * HD_ + ocol + n * 8]       = packh2(oacc[n][0], oacc[n][1]);
        *(uint32_t*)&Obp[(size_t)(orow + 8) * HD_ + ocol + n * 8] = packh2(oacc[n][2], oacc[n][3]);
    }
}

// ==========================================================================
extern "C" void kernel_launch(void* const* d_in, const int* in_sizes, int n_in,
                              void* d_out, int out_size)
{
    const float* X  = (const float*)d_in[0];
    const float* Wq = (const float*)d_in[1];
    const float* Wk = (const float*)d_in[2];
    const float* Wv = (const float*)d_in[3];
    const float* We = (const float*)d_in[4];
    const float* be = (const float*)d_in[5];
    const float* Wf = (const float*)d_in[6];
    const float* bf = (const float*)d_in[7];
    const float* Wo = (const float*)d_in[8];
    const float* bo = (const float*)d_in[9];
    float* out = (float*)d_out;

    __half *Xb, *Xs, *Wqb, *Wqs, *Wkb, *Wks, *Wvb, *Wvs, *Web, *Wes, *Wfb, *Wfs, *Wob, *Wos;
    __half *Qb, *Qs, *Ktb, *Kts, *Vtb, *Vts, *KEbp, *KEsp, *VFbp, *VFsp, *Obp;
    float* Pp;
    cudaGetSymbolAddress((void**)&Xb,  h_Xb);  cudaGetSymbolAddress((void**)&Xs,  h_Xs);
    cudaGetSymbolAddress((void**)&Wqb, h_Wqb); cudaGetSymbolAddress((void**)&Wqs, h_Wqs);
    cudaGetSymbolAddress((void**)&Wkb, h_Wkb); cudaGetSymbolAddress((void**)&Wks, h_Wks);
    cudaGetSymbolAddress((void**)&Wvb, h_Wvb); cudaGetSymbolAddress((void**)&Wvs, h_Wvs);
    cudaGetSymbolAddress((void**)&Web, h_Web); cudaGetSymbolAddress((void**)&Wes, h_Wes);
    cudaGetSymbolAddress((void**)&Wfb, h_Wfb); cudaGetSymbolAddress((void**)&Wfs, h_Wfs);
    cudaGetSymbolAddress((void**)&Wob, h_Wob); cudaGetSymbolAddress((void**)&Wos, h_Wos);
    cudaGetSymbolAddress((void**)&Qb,  h_Qb);  cudaGetSymbolAddress((void**)&Qs,  h_Qs);
    cudaGetSymbolAddress((void**)&Ktb, h_Ktb); cudaGetSymbolAddress((void**)&Kts, h_Kts);
    cudaGetSymbolAddress((void**)&Vtb, h_Vtb); cudaGetSymbolAddress((void**)&Vts, h_Vts);
    cudaGetSymbolAddress((void**)&KEbp, h_KEb); cudaGetSymbolAddress((void**)&KEsp, h_KEs);
    cudaGetSymbolAddress((void**)&VFbp, h_VFb); cudaGetSymbolAddress((void**)&VFsp, h_VFs);
    cudaGetSymbolAddress((void**)&Obp, h_Ob);
    cudaGetSymbolAddress((void**)&Pp,  g_part);

    cudaFuncSetAttribute(hgemm<0, 0>, cudaFuncAttributeMaxDynamicSharedMemorySize, GEMM_SMEM);
    cudaFuncSetAttribute(hgemm<0, 1>, cudaFuncAttributeMaxDynamicSharedMemorySize, GEMM_SMEM);
    cudaFuncSetAttribute(hgemm<1, 0>, cudaFuncAttributeMaxDynamicSharedMemorySize, GEMM_SMEM);
    cudaFuncSetAttribute(attn_mma, cudaFuncAttributeMaxDynamicSharedMemorySize, ATT_SMEM);

    // ---- pre-split inputs
    split_arr<<<M_ * C_ / 4 / 256, 256>>>(X, Xb, Xs, M_ * C_ / 4);
    split6<<<dim3(HD_ * C_ / 4 / 256, 6), 256>>>(
        Wq, Wqb, Wqs, Wk, Wkb, Wks, Wv, Wvb, Wvs,
        We, Web, Wes, Wf, Wfb, Wfs, Wo, Wob, Wos);

    // ---- Q = Xb * (Wq)^T -> split halves        [8192, 1024]
    hgemm<1, 0><<<dim3(8, 64, 1), 256, GEMM_SMEM>>>(Xb, Wqb, Wqs, nullptr,
        nullptr, Qb, Qs, 1024, 1024, 1024, 1024, 0, 0, 0, 0);
    // ---- Kt[b] = Wkb * (X_b)^T -> halves        [1024, 4096] per b
    hgemm<1, 0><<<dim3(32, 8, B_), 256, GEMM_SMEM>>>(Wkb, Xb, Xs, nullptr,
        nullptr, Ktb, Kts, 1024, 1024, 4096, 1024, 0, (long)N_ * C_, (long)HD_ * N_, 0);
    // ---- Vt[b] = Wvb * (X_b)^T -> halves
    hgemm<1, 0><<<dim3(32, 8, B_), 256, GEMM_SMEM>>>(Wvb, Xb, Xs, nullptr,
        nullptr, Vtb, Vts, 1024, 1024, 4096, 1024, 0, (long)N_ * C_, (long)HD_ * N_, 0);
    // ---- KE partials (split-K x4): Web * (Kt)^T -> fp32   [256, 1024]
    hgemm<0, 0><<<dim3(8, 2, 8), 256, GEMM_SMEM>>>(Web, Ktb, Kts, nullptr,
        Pp, nullptr, nullptr, 4096, 4096, 1024, 1024, 0, (long)HD_ * N_, (long)K_ * HD_, 1);
    reduce_split<<<dim3((K_ * HD_ / 4) / 256, B_), 256>>>(Pp, be, KEbp, KEsp, HD_, 0);
    // ---- VFt partials (split-K x4): Vtb * (Wf)^T -> fp32  [1024, 256]
    hgemm<0, 0><<<dim3(2, 8, 8), 256, GEMM_SMEM>>>(Vtb, Wfb, Wfs, nullptr,
        Pp, nullptr, nullptr, 4096, 4096, 256, 1024, (long)HD_ * N_, 0, (long)HD_ * K_, 1);
    reduce_split<<<dim3((HD_ * K_ / 4) / 256, B_), 256>>>(Pp, bf, VFbp, VFsp, K_, 1);
    // ---- fused attention -> O fp16
    attn_mma<<<dim3(N_ / 128, H_, B_), 256, ATT_SMEM>>>(Qb, KEbp, KEsp, VFbp, VFsp, Obp);
    // ---- out = Ob * (Wo)^T + bo                  [8192, 1024] fp32
    hgemm<0, 1><<<dim3(8, 64, 1), 256, GEMM_SMEM>>>(Obp, Wob, Wos, bo,
        out, nullptr, nullptr, 1024, 1024, 1024, 1024, 0, 0, 0, 0);
}

// round 10
// speedup vs baseline: 1.7085x; 1.1034x over previous
#include <cuda_runtime.h>
#include <cuda_fp16.h>
#include <cstdint>

#define B_  2
#define N_  4096
#define C_  1024
#define H_  16
#define D_  64
#define K_  256
#define HD_ 1024
#define M_  8192

// ---------------- persistent split (big/small) fp16 buffers -------------
__device__ __half h_Xb [M_ * C_],    h_Xs [M_ * C_];
__device__ __half h_Wqb[HD_ * C_],   h_Wqs[HD_ * C_];
__device__ __half h_Wkb[HD_ * C_],   h_Wks[HD_ * C_];
__device__ __half h_Wvb[HD_ * C_],   h_Wvs[HD_ * C_];
__device__ __half h_Web[K_ * N_],    h_Wes[K_ * N_];
__device__ __half h_Wfb[K_ * N_],    h_Wfs[K_ * N_];
__device__ __half h_Wob[C_ * HD_],   h_Wos[C_ * HD_];
__device__ __half h_Qb [M_ * HD_],   h_Qs [M_ * HD_];
__device__ __half h_Ktb[B_ * HD_ * N_], h_Kts[B_ * HD_ * N_];
__device__ __half h_Vtb[B_ * HD_ * N_], h_Vts[B_ * HD_ * N_];
__device__ __half h_KEb[B_ * K_ * HD_], h_KEs[B_ * K_ * HD_];
__device__ __half h_VFb[B_ * HD_ * K_], h_VFs[B_ * HD_ * K_];
__device__ __half h_Ob [M_ * HD_];
__device__ float  g_part[16 * K_ * HD_];   // KE slices 0-7, VF slices 8-15

#define DEV __device__ __forceinline__

DEV uint32_t su32(const void* p) {
    uint32_t a;
    asm("{ .reg .u64 t; cvta.to.shared.u64 t, %1; cvt.u32.u64 %0, t; }" : "=r"(a) : "l"(p));
    return a;
}
DEV void splitf(float x, float y, uint32_t& bo, uint32_t& so) {
    __half hx = __float2half_rn(x), hy = __float2half_rn(y);
    __half2 hb = __halves2half2(hx, hy);
    bo = *(uint32_t*)&hb;
    __half2 hs = __floats2half2_rn(x - __half2float(hx), y - __half2float(hy));
    so = *(uint32_t*)&hs;
}
DEV uint32_t packh2(float x, float y) {
    __half2 h = __floats2half2_rn(x, y);
    return *(uint32_t*)&h;
}

#define CP16(dst, src) asm volatile("cp.async.cg.shared.global [%0], [%1], 16;" :: "r"(dst), "l"(src) : "memory")
#define CPCOMMIT() asm volatile("cp.async.commit_group;" ::: "memory")
#define CPWAIT(n)  asm volatile("cp.async.wait_group %0;" :: "n"(n) : "memory")

#define LDM4(r, a) \
    asm volatile("ldmatrix.sync.aligned.m8n8.x4.shared.b16 {%0,%1,%2,%3}, [%4];" \
        : "=r"((r)[0]), "=r"((r)[1]), "=r"((r)[2]), "=r"((r)[3]) : "r"(a))

DEV void mma16816(float* d, const uint32_t* a, const uint32_t* b) {
    asm volatile("mma.sync.aligned.m16n8k16.row.col.f32.f16.f16.f32 "
        "{%0,%1,%2,%3}, {%4,%5,%6,%7}, {%8,%9}, {%0,%1,%2,%3};"
        : "+f"(d[0]), "+f"(d[1]), "+f"(d[2]), "+f"(d[3])
        : "r"(a[0]), "r"(a[1]), "r"(a[2]), "r"(a[3]), "r"(b[0]), "r"(b[1]));
}

// swizzled byte offset inside a 128x32-half tile (rows of 64B, 16B chunks)
DEV uint32_t tswz(int r, int ch) { return (r << 6) | (((ch ^ ((r >> 1) & 3)) & 3) << 4); }

// ==========================================================================
// one split pass for all fp32 inputs: X (8192 blocks) + 6 weights (1024 ea)
// ==========================================================================
__global__ void split_all(
    const float* X,  __half* Xb,  __half* Xs,
    const float* W0, __half* W0b, __half* W0s,
    const float* W1, __half* W1b, __half* W1s,
    const float* W2, __half* W2b, __half* W2s,
    const float* W3, __half* W3b, __half* W3s,
    const float* W4, __half* W4b, __half* W4s,
    const float* W5, __half* W5b, __half* W5s)
{
    const int bid = blockIdx.x;
    const float* in; __half *ob, *os; int base;
    if (bid < 8192) { in = X; ob = Xb; os = Xs; base = bid; }
    else {
        const int t = bid - 8192, w = t >> 10;
        base = t & 1023;
        in = (w == 0) ? W0 : (w == 1) ? W1 : (w == 2) ? W2 : (w == 3) ? W3 : (w == 4) ? W4 : W5;
        ob = (w == 0) ? W0b : (w == 1) ? W1b : (w == 2) ? W2b : (w == 3) ? W3b : (w == 4) ? W4b : W5b;
        os = (w == 0) ? W0s : (w == 1) ? W1s : (w == 2) ? W2s : (w == 3) ? W3s : (w == 4) ? W4s : W5s;
    }
    const int i = base * 256 + threadIdx.x;
    float4 v = ((const float4*)in)[i];
    uint32_t b0, s0, b1, s1;
    splitf(v.x, v.y, b0, s0);
    splitf(v.z, v.w, b1, s1);
    ((uint2*)ob)[i] = make_uint2(b0, b1);
    ((uint2*)os)[i] = make_uint2(s0, s1);
}

// ==========================================================================
// shared GEMM body: C[128,128 tile] = Ab * (Bb+Bs)^T, K=1024 (NK=32)
// cp.async 3-stage, swizzled, 2 CTAs/SM. EPI: 0=fp32 (+opt col bias), 1=split
// ==========================================================================
#define GEMM_SMEM 73728   // 3 stages x 24 KB

template<int EPI, int BIASCOL>
DEV void gemm_body(const __half* __restrict__ Agb,
                   const __half* __restrict__ Bgb,
                   const __half* __restrict__ Bgs,
                   const float* __restrict__ bias,
                   float* __restrict__ Cf,
                   __half* __restrict__ Cbh, __half* __restrict__ Csh,
                   int ldA, int ldB, int ldC,
                   int crow0, int ccol0, __half* sh)
{
    const int tid = threadIdx.x, wid = tid >> 5, lane = tid & 31;
    const uint32_t shb = su32(sh);
    const int wm = (wid >> 2) * 64, wn = (wid & 3) * 32;

    float acc[4][4][4];
#pragma unroll
    for (int m = 0; m < 4; m++)
#pragma unroll
        for (int n = 0; n < 4; n++)
#pragma unroll
            for (int j = 0; j < 4; j++) acc[m][n][j] = 0.f;

    // stage layout (bytes): Ab@0, Bb@8192, Bs@16384; stage stride 24576
    auto PREFETCH = [&](int kt, int s) {
        const uint32_t st = shb + s * 24576;
        const int kc = kt * 32;
#pragma unroll
        for (int p = 0; p < 2; p++) {
            const int id = p * 256 + tid;
            const int r = id >> 2, c = id & 3;
            const uint32_t d = st + tswz(r, c);
            const size_t ga = (size_t)r * ldA + kc + c * 8;
            const size_t gb = (size_t)r * ldB + kc + c * 8;
            CP16(d,         Agb + ga);
            CP16(d +  8192, Bgb + gb);
            CP16(d + 16384, Bgs + gb);
        }
    };

    auto COMPUTE = [&](int s) {
        const uint32_t base = shb + s * 24576;
#pragma unroll
        for (int ks2 = 0; ks2 < 2; ks2++) {
            uint32_t ab[4][4];
#pragma unroll
            for (int m = 0; m < 4; m++) {
                const int r = wm + m * 16 + (lane & 15);
                const int ch = ks2 * 2 + (lane >> 4);
                LDM4(ab[m], base + tswz(r, ch));
            }
#pragma unroll
            for (int np = 0; np < 2; np++) {
                const int r = wn + np * 16 + (lane & 7) + 8 * (lane >> 4);
                const int ch = ks2 * 2 + ((lane >> 3) & 1);
                const uint32_t bd = base + 8192 + tswz(r, ch);
                uint32_t bb[4], bs[4];
                LDM4(bb, bd);
                LDM4(bs, bd + 8192);
#pragma unroll
                for (int m = 0; m < 4; m++) {
                    mma16816(acc[m][2 * np],     ab[m], bb);
                    mma16816(acc[m][2 * np],     ab[m], bs);
                    mma16816(acc[m][2 * np + 1], ab[m], bb + 2);
                    mma16816(acc[m][2 * np + 1], ab[m], bs + 2);
                }
            }
        }
    };

    const int NK = 32;
    PREFETCH(0, 0); CPCOMMIT();
    PREFETCH(1, 1); CPCOMMIT();
    int sc = 0, sp = 2;
    for (int kt = 0; kt < NK; kt++) {
        if (kt + 2 < NK) CPWAIT(1); else CPWAIT(0);
        __syncthreads();
        if (kt + 2 < NK) { PREFETCH(kt + 2, sp); CPCOMMIT(); }
        COMPUTE(sc);
        sc = (sc == 2) ? 0 : sc + 1;
        sp = (sp == 2) ? 0 : sp + 1;
    }

    const int row0 = crow0 + wm + (lane >> 2);
    const int col0 = ccol0 + wn + 2 * (lane & 3);
#pragma unroll
    for (int m = 0; m < 4; m++) {
#pragma unroll
        for (int n = 0; n < 4; n++) {
            const int r = row0 + m * 16, c = col0 + n * 8;
            float v0 = acc[m][n][0], v1 = acc[m][n][1];
            float v2 = acc[m][n][2], v3 = acc[m][n][3];
            if (EPI == 0) {
                if (BIASCOL) {
                    const float bc0 = __ldg(&bias[c]), bc1 = __ldg(&bias[c + 1]);
                    v0 += bc0; v1 += bc1; v2 += bc0; v3 += bc1;
                }
                *(float2*)&Cf[(size_t)r * ldC + c]       = make_float2(v0, v1);
                *(float2*)&Cf[(size_t)(r + 8) * ldC + c] = make_float2(v2, v3);
            } else {
                uint32_t b0, s0, b1, s1;
                splitf(v0, v1, b0, s0);
                splitf(v2, v3, b1, s1);
                *(uint32_t*)&Cbh[(size_t)r * ldC + c]       = b0;
                *(uint32_t*)&Csh[(size_t)r * ldC + c]       = s0;
                *(uint32_t*)&Cbh[(size_t)(r + 8) * ldC + c] = b1;
                *(uint32_t*)&Csh[(size_t)(r + 8) * ldC + c] = s1;
            }
        }
    }
}

// ==========================================================================
// merged Q + Kt + Vt: 1536 CTAs in one launch
//   [0,512):     Q  = Xb * (Wq)^T        -> (Qb,Qs)   [8192,1024]
//   [512,1024):  Kt = Wkb * (X_b)^T      -> (Ktb,Kts) [1024,4096] per b
//   [1024,1536): Vt = Wvb * (X_b)^T      -> (Vtb,Vts)
// ==========================================================================
__global__ void __launch_bounds__(256, 2)
qkv_gemm(const __half* __restrict__ Xb, const __half* __restrict__ Xs,
         const __half* __restrict__ Wqb, const __half* __restrict__ Wqs,
         const __half* __restrict__ Wkb, const __half* __restrict__ Wvb,
         __half* Qb, __half* Qs, __half* Ktb, __half* Kts,
         __half* Vtb, __half* Vts)
{
    extern __shared__ __half sh[];
    const int idx = blockIdx.x;
    if (idx < 512) {
        const int bx = idx & 7, by = idx >> 3;
        gemm_body<1, 0>(Xb + (size_t)by * 128 * 1024,
                        Wqb + (size_t)bx * 128 * 1024,
                        Wqs + (size_t)bx * 128 * 1024,
                        nullptr, nullptr, Qb, Qs,
                        1024, 1024, 1024, by * 128, bx * 128, sh);
    } else {
        const int t = idx - 512;
        const int kv = t >> 9, r = t & 511;
        const int bx = r & 31, by = (r >> 5) & 7, b = r >> 8;
        const __half* A  = (kv ? Wvb : Wkb) + (size_t)by * 128 * 1024;
        const __half* Bb = Xb + (size_t)b * N_ * C_ + (size_t)bx * 128 * 1024;
        const __half* Bs = Xs + (size_t)b * N_ * C_ + (size_t)bx * 128 * 1024;
        __half* Cb = (kv ? Vtb : Ktb) + (size_t)b * HD_ * N_;
        __half* Cs = (kv ? Vts : Kts) + (size_t)b * HD_ * N_;
        gemm_body<1, 0>(A, Bb, Bs, nullptr, nullptr, Cb, Cs,
                        1024, 1024, 4096, by * 128, bx * 128, sh);
    }
}

// ==========================================================================
// merged KE + VF split-K partials: 256 CTAs in one launch -> g_part
//   [0,128):   KE[z] = Web[:,ks] * Kt[b][:,ks]^T  [256,1024] -> slices 0-7
//   [128,256): VF[z] = Vtb[b][:,ks] * Wf[:,ks]^T  [1024,256] -> slices 8-15
// ==========================================================================
__global__ void __launch_bounds__(256, 2)
kevf_gemm(const __half* __restrict__ Web,
          const __half* __restrict__ Ktb, const __half* __restrict__ Kts,
          const __half* __restrict__ Vtb,
          const __half* __restrict__ Wfb, const __half* __restrict__ Wfs,
          float* part)
{
    extern __shared__ __half sh[];
    const int idx = blockIdx.x;
    if (idx < 128) {
        const int bx = idx & 7, by = (idx >> 3) & 1, z = idx >> 4;
        const int b = z >> 2, ks = z & 3;
        const __half* A  = Web + ks * 1024 + (size_t)by * 128 * 4096;
        const __half* Bb = Ktb + (size_t)b * HD_ * N_ + ks * 1024 + (size_t)bx * 128 * 4096;
        const __half* Bs = Kts + (size_t)b * HD_ * N_ + ks * 1024 + (size_t)bx * 128 * 4096;
        gemm_body<0, 0>(A, Bb, Bs, nullptr,
                        part + (size_t)z * K_ * HD_, nullptr, nullptr,
                        4096, 4096, 1024, by * 128, bx * 128, sh);
    } else {
        const int t = idx - 128;
        const int bx = t & 1, by = (t >> 1) & 7, z = t >> 4;
        const int b = z >> 2, ks = z & 3;
        const __half* A  = Vtb + (size_t)b * HD_ * N_ + ks * 1024 + (size_t)by * 128 * 4096;
        const __half* Bb = Wfb + ks * 1024 + (size_t)bx * 128 * 4096;
        const __half* Bs = Wfs + ks * 1024 + (size_t)bx * 128 * 4096;
        gemm_body<0, 0>(A, Bb, Bs, nullptr,
                        part + (size_t)(8 + z) * K_ * HD_, nullptr, nullptr,
                        4096, 4096, 256, by * 128, bx * 128, sh);
    }
}

// ==========================================================================
// out projection (stand-alone: depends on attention output)
// ==========================================================================
__global__ void __launch_bounds__(256, 2)
out_gemm(const __half* __restrict__ Ob_,
         const __half* __restrict__ Wob, const __half* __restrict__ Wos,
         const float* __restrict__ bo, float* __restrict__ out)
{
    extern __shared__ __half sh[];
    const int bx = blockIdx.x, by = blockIdx.y;
    gemm_body<0, 1>(Ob_ + (size_t)by * 128 * 1024,
                    Wob + (size_t)bx * 128 * 1024,
                    Wos + (size_t)bx * 128 * 1024,
                    bo, out, nullptr, nullptr,
                    1024, 1024, 1024, by * 128, bx * 128, sh);
}

// ==========================================================================
// merged split-K reduce + bias -> split halves (z=0: KE, z=1: VF)
// ==========================================================================
__global__ void reduce2(const float* __restrict__ part,
                        const float* __restrict__ be, const float* __restrict__ bf,
                        __half* KEb, __half* KEs, __half* VFb, __half* VFs)
{
    const int per = (K_ * HD_) / 4;
    const int i = blockIdx.x * 256 + threadIdx.x;
    const int b = blockIdx.y;
    const int which = blockIdx.z;

    const float* bias = which ? bf : be;
    __half* ob = which ? VFb : KEb;
    __half* os = which ? VFs : KEs;
    const int cols = which ? K_ : HD_;
    const float4* p = (const float4*)(part + (which ? (size_t)8 * K_ * HD_ : 0))
                      + (size_t)b * 4 * per;

    float4 v = p[i];
    float4 v1 = p[per + i], v2 = p[2 * per + i], v3 = p[3 * per + i];
    v.x += v1.x + v2.x + v3.x; v.y += v1.y + v2.y + v3.y;
    v.z += v1.z + v2.z + v3.z; v.w += v1.w + v2.w + v3.w;
    const int e = i * 4;
    if (which) {           // per-column bias
        const int c = e % cols;
        v.x += bias[c]; v.y += bias[c + 1]; v.z += bias[c + 2]; v.w += bias[c + 3];
    } else {               // per-row bias
        const float bb = bias[e / cols];
        v.x += bb; v.y += bb; v.z += bb; v.w += bb;
    }
    uint32_t b0, s0, b1, s1;
    splitf(v.x, v.y, b0, s0);
    splitf(v.z, v.w, b1, s1);
    ((uint2*)ob)[(size_t)b * per + i] = make_uint2(b0, b1);
    ((uint2*)os)[(size_t)b * per + i] = make_uint2(s0, s1);
}

// ==========================================================================
// Fused attention: CTA = (128 rows, head h, batch b), 8 warps
// scores = Qb * (KEb+KEs)^T; softmax; O = P16 * (VFb+VFs)^T; store O fp16
// ==========================================================================
#define QSTR 72
#define VSTR 264
#define OQB 0
#define OKB (128 * QSTR)
#define OKS (OKB + 256 * QSTR)
#define OVB (OKS + 256 * QSTR)
#define OVS (OVB + 64 * VSTR)
#define ATT_SMEM ((OVS + 64 * VSTR) * 2)   // 159744 bytes

__global__ void __launch_bounds__(256, 1)
attn_mma(const __half* __restrict__ Qb, const __half* __restrict__ KEb,
         const __half* __restrict__ KEs, const __half* __restrict__ VFb,
         const __half* __restrict__ VFs, __half* __restrict__ Ob)
{
    extern __shared__ __half sh[];
    const int tid = threadIdx.x, wid = tid >> 5, lane = tid & 31;
    const int b = blockIdx.z, h = blockIdx.y, n0 = blockIdx.x * 128;
    const uint32_t shb = su32(sh);

    const __half* Qgb = Qb  + ((size_t)(b * N_ + n0)) * HD_ + h * D_;
    const __half* Kgb = KEb + ((size_t)b * K_) * HD_ + h * D_;
    const __half* Kgs = KEs + ((size_t)b * K_) * HD_ + h * D_;
    const __half* Vgb = VFb + ((size_t)(b * HD_ + h * D_)) * K_;
    const __half* Vgs = VFs + ((size_t)(b * HD_ + h * D_)) * K_;

#pragma unroll
    for (int p = 0; p < 4; p++) {         // Q: 128 rows x 8 chunks (big only)
        const int id = p * 256 + tid;
        const int r = id >> 3, c = id & 7;
        CP16(shb + OQB * 2 + (r * QSTR + c * 8) * 2, Qgb + (size_t)r * HD_ + c * 8);
    }
#pragma unroll
    for (int p = 0; p < 8; p++) {         // KE: 256 rows x 8 chunks
        const int id = p * 256 + tid;
        const int r = id >> 3, c = id & 7;
        const size_t g = (size_t)r * HD_ + c * 8;
        const uint32_t d = (r * QSTR + c * 8) * 2;
        CP16(shb + OKB * 2 + d, Kgb + g);
        CP16(shb + OKS * 2 + d, Kgs + g);
    }
#pragma unroll
    for (int p = 0; p < 8; p++) {         // VF: 64 rows x 32 chunks
        const int id = p * 256 + tid;
        const int r = id >> 5, c = id & 31;
        const size_t g = (size_t)r * K_ + c * 8;
        const uint32_t d = (r * VSTR + c * 8) * 2;
        CP16(shb + OVB * 2 + d, Vgb + g);
        CP16(shb + OVS * 2 + d, Vgs + g);
    }
    CPCOMMIT();
    CPWAIT(0);
    __syncthreads();

    // ---- scores
    float sacc[32][4];
#pragma unroll
    for (int j = 0; j < 32; j++)
#pragma unroll
        for (int q = 0; q < 4; q++) sacc[j][q] = 0.f;

    const int r0 = wid * 16;
    const uint32_t aoff = ((r0 + (lane & 15)) * QSTR + 8 * (lane >> 4)) * 2;
    const uint32_t boff = (((lane & 7) + 8 * (lane >> 4)) * QSTR + 8 * ((lane >> 3) & 1)) * 2;

#pragma unroll
    for (int ks = 0; ks < 64; ks += 16) {
        uint32_t ab[4];
        LDM4(ab, shb + OQB * 2 + aoff + ks * 2);
#pragma unroll
        for (int np = 0; np < 16; np++) {
            uint32_t kb[4], ksm[4];
            const uint32_t bd = boff + (np * 16 * QSTR + ks) * 2;
            LDM4(kb,  shb + OKB * 2 + bd);
            LDM4(ksm, shb + OKS * 2 + bd);
            mma16816(sacc[2 * np],     ab, kb);
            mma16816(sacc[2 * np],     ab, ksm);
            mma16816(sacc[2 * np + 1], ab, kb + 2);
            mma16816(sacc[2 * np + 1], ab, ksm + 2);
        }
    }

    // ---- softmax
    float mx0 = -1e30f, mx1 = -1e30f;
#pragma unroll
    for (int j = 0; j < 32; j++) {
        mx0 = fmaxf(mx0, fmaxf(sacc[j][0], sacc[j][1]));
        mx1 = fmaxf(mx1, fmaxf(sacc[j][2], sacc[j][3]));
    }
    mx0 = fmaxf(mx0, __shfl_xor_sync(0xffffffffu, mx0, 1));
    mx0 = fmaxf(mx0, __shfl_xor_sync(0xffffffffu, mx0, 2));
    mx1 = fmaxf(mx1, __shfl_xor_sync(0xffffffffu, mx1, 1));
    mx1 = fmaxf(mx1, __shfl_xor_sync(0xffffffffu, mx1, 2));
    float sum0 = 0.f, sum1 = 0.f;
#pragma unroll
    for (int j = 0; j < 32; j++) {
        float e0 = __expf((sacc[j][0] - mx0) * 0.125f);
        float e1 = __expf((sacc[j][1] - mx0) * 0.125f);
        float e2 = __expf((sacc[j][2] - mx1) * 0.125f);
        float e3 = __expf((sacc[j][3] - mx1) * 0.125f);
        sacc[j][0] = e0; sacc[j][1] = e1; sacc[j][2] = e2; sacc[j][3] = e3;
        sum0 += e0 + e1; sum1 += e2 + e3;
    }
    sum0 += __shfl_xor_sync(0xffffffffu, sum0, 1);
    sum0 += __shfl_xor_sync(0xffffffffu, sum0, 2);
    sum1 += __shfl_xor_sync(0xffffffffu, sum1, 1);
    sum1 += __shfl_xor_sync(0xffffffffu, sum1, 2);
    const float inv0 = 1.0f / sum0, inv1 = 1.0f / sum1;
#pragma unroll
    for (int j = 0; j < 32; j++) {
        sacc[j][0] *= inv0; sacc[j][1] *= inv0;
        sacc[j][2] *= inv1; sacc[j][3] *= inv1;
    }

    // ---- PV (P as plain fp16)
    float oacc[8][4];
#pragma unroll
    for (int n = 0; n < 8; n++)
#pragma unroll
        for (int q = 0; q < 4; q++) oacc[n][q] = 0.f;

#pragma unroll
    for (int kt = 0; kt < 16; kt++) {
        uint32_t pa[4];
        pa[0] = packh2(sacc[2 * kt][0],     sacc[2 * kt][1]);
        pa[1] = packh2(sacc[2 * kt][2],     sacc[2 * kt][3]);
        pa[2] = packh2(sacc[2 * kt + 1][0], sacc[2 * kt + 1][1]);
        pa[3] = packh2(sacc[2 * kt + 1][2], sacc[2 * kt + 1][3]);
#pragma unroll
        for (int np = 0; np < 4; np++) {
            const uint32_t bd = (((lane & 7) + 8 * (lane >> 4) + np * 16) * VSTR
                                 + kt * 16 + 8 * ((lane >> 3) & 1)) * 2;
            uint32_t vb[4], vs[4];
            LDM4(vb, shb + OVB * 2 + bd);
            LDM4(vs, shb + OVS * 2 + bd);
            mma16816(oacc[2 * np],     pa, vb);
            mma16816(oacc[2 * np],     pa, vs);
            mma16816(oacc[2 * np + 1], pa, vb + 2);
            mma16816(oacc[2 * np + 1], pa, vs + 2);
        }
    }

    // ---- store O (fp16 big only; out-proj uses A = Ob)
    const int orow = n0 + r0 + (lane >> 2);
    const int ocol = h * D_ + 2 * (lane & 3);
    __half* Obp = Ob + ((size_t)b * N_) * HD_;
#pragma unroll
    for (int n = 0; n < 8; n++) {
        *(uint32_t*)&Obp[(size_t)orow * HD_ + ocol + n * 8]       = packh2(oacc[n][0], oacc[n][1]);
        *(uint32_t*)&Obp[(size_t)(orow + 8) * HD_ + ocol + n * 8] = packh2(oacc[n][2], oacc[n][3]);
    }
}

// ==========================================================================
extern "C" void kernel_launch(void* const* d_in, const int* in_sizes, int n_in,
                              void* d_out, int out_size)
{
    const float* X  = (const float*)d_in[0];
    const float* Wq = (const float*)d_in[1];
    const float* Wk = (const float*)d_in[2];
    const float* Wv = (const float*)d_in[3];
    const float* We = (const float*)d_in[4];
    const float* be = (const float*)d_in[5];
    const float* Wf = (const float*)d_in[6];
    const float* bf = (const float*)d_in[7];
    const float* Wo = (const float*)d_in[8];
    const float* bo = (const float*)d_in[9];
    float* out = (float*)d_out;

    __half *Xb, *Xs, *Wqb, *Wqs, *Wkb, *Wks, *Wvb, *Wvs, *Web, *Wes, *Wfb, *Wfs, *Wob, *Wos;
    __half *Qb, *Qs, *Ktb, *Kts, *Vtb, *Vts, *KEbp, *KEsp, *VFbp, *VFsp, *Obp;
    float* Pp;
    cudaGetSymbolAddress((void**)&Xb,  h_Xb);  cudaGetSymbolAddress((void**)&Xs,  h_Xs);
    cudaGetSymbolAddress((void**)&Wqb, h_Wqb); cudaGetSymbolAddress((void**)&Wqs, h_Wqs);
    cudaGetSymbolAddress((void**)&Wkb, h_Wkb); cudaGetSymbolAddress((void**)&Wks, h_Wks);
    cudaGetSymbolAddress((void**)&Wvb, h_Wvb); cudaGetSymbolAddress((void**)&Wvs, h_Wvs);
    cudaGetSymbolAddress((void**)&Web, h_Web); cudaGetSymbolAddress((void**)&Wes, h_Wes);
    cudaGetSymbolAddress((void**)&Wfb, h_Wfb); cudaGetSymbolAddress((void**)&Wfs, h_Wfs);
    cudaGetSymbolAddress((void**)&Wob, h_Wob); cudaGetSymbolAddress((void**)&Wos, h_Wos);
    cudaGetSymbolAddress((void**)&Qb,  h_Qb);  cudaGetSymbolAddress((void**)&Qs,  h_Qs);
    cudaGetSymbolAddress((void**)&Ktb, h_Ktb); cudaGetSymbolAddress((void**)&Kts, h_Kts);
    cudaGetSymbolAddress((void**)&Vtb, h_Vtb); cudaGetSymbolAddress((void**)&Vts, h_Vts);
    cudaGetSymbolAddress((void**)&KEbp, h_KEb); cudaGetSymbolAddress((void**)&KEsp, h_KEs);
    cudaGetSymbolAddress((void**)&VFbp, h_VFb); cudaGetSymbolAddress((void**)&VFsp, h_VFs);
    cudaGetSymbolAddress((void**)&Obp, h_Ob);
    cudaGetSymbolAddress((void**)&Pp,  g_part);

    cudaFuncSetAttribute(qkv_gemm,  cudaFuncAttributeMaxDynamicSharedMemorySize, GEMM_SMEM);
    cudaFuncSetAttribute(kevf_gemm, cudaFuncAttributeMaxDynamicSharedMemorySize, GEMM_SMEM);
    cudaFuncSetAttribute(out_gemm,  cudaFuncAttributeMaxDynamicSharedMemorySize, GEMM_SMEM);
    cudaFuncSetAttribute(attn_mma,  cudaFuncAttributeMaxDynamicSharedMemorySize, ATT_SMEM);

    // 1) split X + all six weights in one launch (8192 + 6*1024 blocks)
    split_all<<<8192 + 6 * 1024, 256>>>(
        X, Xb, Xs,
        Wq, Wqb, Wqs, Wk, Wkb, Wks, Wv, Wvb, Wvs,
        We, Web, Wes, Wf, Wfb, Wfs, Wo, Wob, Wos);

    // 2) merged Q + Kt + Vt (1536 CTAs)
    qkv_gemm<<<1536, 256, GEMM_SMEM>>>(Xb, Xs, Wqb, Wqs, Wkb, Wvb,
                                       Qb, Qs, Ktb, Kts, Vtb, Vts);

    // 3) merged KE + VF split-K partials (256 CTAs)
    kevf_gemm<<<256, 256, GEMM_SMEM>>>(Web, Ktb, Kts, Vtb, Wfb, Wfs, Pp);

    // 4) merged reduce (+bias) -> split halves
    reduce2<<<dim3(256, B_, 2), 256>>>(Pp, be, bf, KEbp, KEsp, VFbp, VFsp);

    // 5) fused attention -> O fp16
    attn_mma<<<dim3(N_ / 128, H_, B_), 256, ATT_SMEM>>>(Qb, KEbp, KEsp, VFbp, VFsp, Obp);

    // 6) out = Ob * (Wo)^T + bo
    out_gemm<<<dim3(8, 64), 256, GEMM_SMEM>>>(Obp, Wob, Wos, bo, out);
}

// round 11
// speedup vs baseline: 1.7099x; 1.0008x over previous
#include <cuda_runtime.h>
#include <cuda_fp16.h>
#include <cstdint>

#define B_  2
#define N_  4096
#define C_  1024
#define H_  16
#define D_  64
#define K_  256
#define HD_ 1024
#define M_  8192

// ---------------- persistent split (big/small) fp16 buffers -------------
__device__ __half h_Xb [M_ * C_],    h_Xs [M_ * C_];
__device__ __half h_Wqb[HD_ * C_],   h_Wqs[HD_ * C_];
__device__ __half h_Wkb[HD_ * C_],   h_Wks[HD_ * C_];
__device__ __half h_Wvb[HD_ * C_],   h_Wvs[HD_ * C_];
__device__ __half h_Web[K_ * N_],    h_Wes[K_ * N_];
__device__ __half h_Wfb[K_ * N_],    h_Wfs[K_ * N_];
__device__ __half h_Wob[C_ * HD_],   h_Wos[C_ * HD_];
__device__ __half h_Qb [M_ * HD_],   h_Qs [M_ * HD_];
__device__ __half h_Ktb[B_ * HD_ * N_], h_Kts[B_ * HD_ * N_];
__device__ __half h_Vtb[B_ * HD_ * N_], h_Vts[B_ * HD_ * N_];
__device__ __half h_KEb[B_ * K_ * HD_], h_KEs[B_ * K_ * HD_];
__device__ __half h_VFb[B_ * HD_ * K_], h_VFs[B_ * HD_ * K_];
__device__ __half h_Ob [M_ * HD_];
__device__ float  g_part[16 * K_ * HD_];   // KE slices 0-7, VF slices 8-15

#define DEV __device__ __forceinline__

DEV uint32_t su32(const void* p) {
    uint32_t a;
    asm("{ .reg .u64 t; cvta.to.shared.u64 t, %1; cvt.u32.u64 %0, t; }" : "=r"(a) : "l"(p));
    return a;
}
DEV void splitf(float x, float y, uint32_t& bo, uint32_t& so) {
    __half hx = __float2half_rn(x), hy = __float2half_rn(y);
    __half2 hb = __halves2half2(hx, hy);
    bo = *(uint32_t*)&hb;
    __half2 hs = __floats2half2_rn(x - __half2float(hx), y - __half2float(hy));
    so = *(uint32_t*)&hs;
}
DEV uint32_t packh2(float x, float y) {
    __half2 h = __floats2half2_rn(x, y);
    return *(uint32_t*)&h;
}

#define CP16(dst, src) asm volatile("cp.async.cg.shared.global [%0], [%1], 16;" :: "r"(dst), "l"(src) : "memory")
#define CPCOMMIT() asm volatile("cp.async.commit_group;" ::: "memory")
#define CPWAIT(n)  asm volatile("cp.async.wait_group %0;" :: "n"(n) : "memory")

#define LDM4(r, a) \
    asm volatile("ldmatrix.sync.aligned.m8n8.x4.shared.b16 {%0,%1,%2,%3}, [%4];" \
        : "=r"((r)[0]), "=r"((r)[1]), "=r"((r)[2]), "=r"((r)[3]) : "r"(a))

DEV void mma16816(float* d, const uint32_t* a, const uint32_t* b) {
    asm volatile("mma.sync.aligned.m16n8k16.row.col.f32.f16.f16.f32 "
        "{%0,%1,%2,%3}, {%4,%5,%6,%7}, {%8,%9}, {%0,%1,%2,%3};"
        : "+f"(d[0]), "+f"(d[1]), "+f"(d[2]), "+f"(d[3])
        : "r"(a[0]), "r"(a[1]), "r"(a[2]), "r"(a[3]), "r"(b[0]), "r"(b[1]));
}

// swizzled byte offset inside a 128x32-half tile (rows of 64B, 16B chunks)
DEV uint32_t tswz(int r, int ch) { return (r << 6) | (((ch ^ ((r >> 1) & 3)) & 3) << 4); }

// ==========================================================================
// one split pass for all fp32 inputs: X (8192 blocks) + 6 weights (1024 ea)
// ==========================================================================
__global__ void split_all(
    const float* X,  __half* Xb,  __half* Xs,
    const float* W0, __half* W0b, __half* W0s,
    const float* W1, __half* W1b, __half* W1s,
    const float* W2, __half* W2b, __half* W2s,
    const float* W3, __half* W3b, __half* W3s,
    const float* W4, __half* W4b, __half* W4s,
    const float* W5, __half* W5b, __half* W5s)
{
    const int bid = blockIdx.x;
    const float* in; __half *ob, *os; int base;
    if (bid < 8192) { in = X; ob = Xb; os = Xs; base = bid; }
    else {
        const int t = bid - 8192, w = t >> 10;
        base = t & 1023;
        in = (w == 0) ? W0 : (w == 1) ? W1 : (w == 2) ? W2 : (w == 3) ? W3 : (w == 4) ? W4 : W5;
        ob = (w == 0) ? W0b : (w == 1) ? W1b : (w == 2) ? W2b : (w == 3) ? W3b : (w == 4) ? W4b : W5b;
        os = (w == 0) ? W0s : (w == 1) ? W1s : (w == 2) ? W2s : (w == 3) ? W3s : (w == 4) ? W4s : W5s;
    }
    const int i = base * 256 + threadIdx.x;
    float4 v = ((const float4*)in)[i];
    uint32_t b0, s0, b1, s1;
    splitf(v.x, v.y, b0, s0);
    splitf(v.z, v.w, b1, s1);
    ((uint2*)ob)[i] = make_uint2(b0, b1);
    ((uint2*)os)[i] = make_uint2(s0, s1);
}

// ==========================================================================
// shared GEMM body: C[128,128 tile] = Ab * (Bb+Bs)^T, K=1024 (NK=32)
// cp.async 4-stage (CPWAIT(2)), swizzled, 2 CTAs/SM.
// MMA issue order de-chains accumulator RAW (bb terms for all accums, then
// bs terms) while preserving per-accumulator operand order (bit-identical).
// EPI: 0=fp32 (+opt col bias), 1=split-half out
// ==========================================================================
#define GEMM_SMEM 98304   // 4 stages x 24 KB

template<int EPI, int BIASCOL>
DEV void gemm_body(const __half* __restrict__ Agb,
                   const __half* __restrict__ Bgb,
                   const __half* __restrict__ Bgs,
                   const float* __restrict__ bias,
                   float* __restrict__ Cf,
                   __half* __restrict__ Cbh, __half* __restrict__ Csh,
                   int ldA, int ldB, int ldC,
                   int crow0, int ccol0, __half* sh)
{
    const int tid = threadIdx.x, wid = tid >> 5, lane = tid & 31;
    const uint32_t shb = su32(sh);
    const int wm = (wid >> 2) * 64, wn = (wid & 3) * 32;

    float acc[4][4][4];
#pragma unroll
    for (int m = 0; m < 4; m++)
#pragma unroll
        for (int n = 0; n < 4; n++)
#pragma unroll
            for (int j = 0; j < 4; j++) acc[m][n][j] = 0.f;

    // stage layout (bytes): Ab@0, Bb@8192, Bs@16384; stage stride 24576
    auto PREFETCH = [&](int kt, int s) {
        const uint32_t st = shb + s * 24576;
        const int kc = kt * 32;
#pragma unroll
        for (int p = 0; p < 2; p++) {
            const int id = p * 256 + tid;
            const int r = id >> 2, c = id & 3;
            const uint32_t d = st + tswz(r, c);
            const size_t ga = (size_t)r * ldA + kc + c * 8;
            const size_t gb = (size_t)r * ldB + kc + c * 8;
            CP16(d,         Agb + ga);
            CP16(d +  8192, Bgb + gb);
            CP16(d + 16384, Bgs + gb);
        }
    };

    auto COMPUTE = [&](int s) {
        const uint32_t base = shb + s * 24576;
#pragma unroll
        for (int ks2 = 0; ks2 < 2; ks2++) {
            uint32_t ab[4][4];
#pragma unroll
            for (int m = 0; m < 4; m++) {
                const int r = wm + m * 16 + (lane & 15);
                const int ch = ks2 * 2 + (lane >> 4);
                LDM4(ab[m], base + tswz(r, ch));
            }
#pragma unroll
            for (int np = 0; np < 2; np++) {
                const int r = wn + np * 16 + (lane & 7) + 8 * (lane >> 4);
                const int ch = ks2 * 2 + ((lane >> 3) & 1);
                const uint32_t bd = base + 8192 + tswz(r, ch);
                uint32_t bb[4], bs[4];
                LDM4(bb, bd);
                LDM4(bs, bd + 8192);
                // bb terms across all 8 accumulators first, then bs terms:
                // same-acc reuse gap = 8 MMAs; per-acc order (bb then bs)
                // preserved -> bit-identical accumulation.
#pragma unroll
                for (int m = 0; m < 4; m++) mma16816(acc[m][2 * np],     ab[m], bb);
#pragma unroll
                for (int m = 0; m < 4; m++) mma16816(acc[m][2 * np + 1], ab[m], bb + 2);
#pragma unroll
                for (int m = 0; m < 4; m++) mma16816(acc[m][2 * np],     ab[m], bs);
#pragma unroll
                for (int m = 0; m < 4; m++) mma16816(acc[m][2 * np + 1], ab[m], bs + 2);
            }
        }
    };

    const int NK = 32;
    PREFETCH(0, 0); CPCOMMIT();
    PREFETCH(1, 1); CPCOMMIT();
    PREFETCH(2, 2); CPCOMMIT();
    int sc = 0, sp = 3;
    for (int kt = 0; kt < NK; kt++) {
        if (kt + 3 < NK) CPWAIT(2); else CPWAIT(0);
        __syncthreads();
        if (kt + 3 < NK) { PREFETCH(kt + 3, sp); CPCOMMIT(); }
        COMPUTE(sc);
        sc = (sc + 1) & 3;
        sp = (sp + 1) & 3;
    }

    const int row0 = crow0 + wm + (lane >> 2);
    const int col0 = ccol0 + wn + 2 * (lane & 3);
#pragma unroll
    for (int m = 0; m < 4; m++) {
#pragma unroll
        for (int n = 0; n < 4; n++) {
            const int r = row0 + m * 16, c = col0 + n * 8;
            float v0 = acc[m][n][0], v1 = acc[m][n][1];
            float v2 = acc[m][n][2], v3 = acc[m][n][3];
            if (EPI == 0) {
                if (BIASCOL) {
                    const float bc0 = __ldg(&bias[c]), bc1 = __ldg(&bias[c + 1]);
                    v0 += bc0; v1 += bc1; v2 += bc0; v3 += bc1;
                }
                *(float2*)&Cf[(size_t)r * ldC + c]       = make_float2(v0, v1);
                *(float2*)&Cf[(size_t)(r + 8) * ldC + c] = make_float2(v2, v3);
            } else {
                uint32_t b0, s0, b1, s1;
                splitf(v0, v1, b0, s0);
                splitf(v2, v3, b1, s1);
                *(uint32_t*)&Cbh[(size_t)r * ldC + c]       = b0;
                *(uint32_t*)&Csh[(size_t)r * ldC + c]       = s0;
                *(uint32_t*)&Cbh[(size_t)(r + 8) * ldC + c] = b1;
                *(uint32_t*)&Csh[(size_t)(r + 8) * ldC + c] = s1;
            }
        }
    }
}

// ==========================================================================
// merged Q + Kt + Vt: 1536 CTAs in one launch
// ==========================================================================
__global__ void __launch_bounds__(256, 2)
qkv_gemm(const __half* __restrict__ Xb, const __half* __restrict__ Xs,
         const __half* __restrict__ Wqb, const __half* __restrict__ Wqs,
         const __half* __restrict__ Wkb, const __half* __restrict__ Wvb,
         __half* Qb, __half* Qs, __half* Ktb, __half* Kts,
         __half* Vtb, __half* Vts)
{
    extern __shared__ __half sh[];
    const int idx = blockIdx.x;
    if (idx < 512) {
        const int bx = idx & 7, by = idx >> 3;
        gemm_body<1, 0>(Xb + (size_t)by * 128 * 1024,
                        Wqb + (size_t)bx * 128 * 1024,
                        Wqs + (size_t)bx * 128 * 1024,
                        nullptr, nullptr, Qb, Qs,
                        1024, 1024, 1024, by * 128, bx * 128, sh);
    } else {
        const int t = idx - 512;
        const int kv = t >> 9, r = t & 511;
        const int bx = r & 31, by = (r >> 5) & 7, b = r >> 8;
        const __half* A  = (kv ? Wvb : Wkb) + (size_t)by * 128 * 1024;
        const __half* Bb = Xb + (size_t)b * N_ * C_ + (size_t)bx * 128 * 1024;
        const __half* Bs = Xs + (size_t)b * N_ * C_ + (size_t)bx * 128 * 1024;
        __half* Cb = (kv ? Vtb : Ktb) + (size_t)b * HD_ * N_;
        __half* Cs = (kv ? Vts : Kts) + (size_t)b * HD_ * N_;
        gemm_body<1, 0>(A, Bb, Bs, nullptr, nullptr, Cb, Cs,
                        1024, 1024, 4096, by * 128, bx * 128, sh);
    }
}

// ==========================================================================
// merged KE + VF split-K partials: 256 CTAs -> g_part
// ==========================================================================
__global__ void __launch_bounds__(256, 2)
kevf_gemm(const __half* __restrict__ Web,
          const __half* __restrict__ Ktb, const __half* __restrict__ Kts,
          const __half* __restrict__ Vtb,
          const __half* __restrict__ Wfb, const __half* __restrict__ Wfs,
          float* part)
{
    extern __shared__ __half sh[];
    const int idx = blockIdx.x;
    if (idx < 128) {
        const int bx = idx & 7, by = (idx >> 3) & 1, z = idx >> 4;
        const int b = z >> 2, ks = z & 3;
        const __half* A  = Web + ks * 1024 + (size_t)by * 128 * 4096;
        const __half* Bb = Ktb + (size_t)b * HD_ * N_ + ks * 1024 + (size_t)bx * 128 * 4096;
        const __half* Bs = Kts + (size_t)b * HD_ * N_ + ks * 1024 + (size_t)bx * 128 * 4096;
        gemm_body<0, 0>(A, Bb, Bs, nullptr,
                        part + (size_t)z * K_ * HD_, nullptr, nullptr,
                        4096, 4096, 1024, by * 128, bx * 128, sh);
    } else {
        const int t = idx - 128;
        const int bx = t & 1, by = (t >> 1) & 7, z = t >> 4;
        const int b = z >> 2, ks = z & 3;
        const __half* A  = Vtb + (size_t)b * HD_ * N_ + ks * 1024 + (size_t)by * 128 * 4096;
        const __half* Bb = Wfb + ks * 1024 + (size_t)bx * 128 * 4096;
        const __half* Bs = Wfs + ks * 1024 + (size_t)bx * 128 * 4096;
        gemm_body<0, 0>(A, Bb, Bs, nullptr,
                        part + (size_t)(8 + z) * K_ * HD_, nullptr, nullptr,
                        4096, 4096, 256, by * 128, bx * 128, sh);
    }
}

// ==========================================================================
// out projection
// ==========================================================================
__global__ void __launch_bounds__(256, 2)
out_gemm(const __half* __restrict__ Ob_,
         const __half* __restrict__ Wob, const __half* __restrict__ Wos,
         const float* __restrict__ bo, float* __restrict__ out)
{
    extern __shared__ __half sh[];
    const int bx = blockIdx.x, by = blockIdx.y;
    gemm_body<0, 1>(Ob_ + (size_t)by * 128 * 1024,
                    Wob + (size_t)bx * 128 * 1024,
                    Wos + (size_t)bx * 128 * 1024,
                    bo, out, nullptr, nullptr,
                    1024, 1024, 1024, by * 128, bx * 128, sh);
}

// ==========================================================================
// merged split-K reduce + bias -> split halves (z=0: KE, z=1: VF)
// ==========================================================================
__global__ void reduce2(const float* __restrict__ part,
                        const float* __restrict__ be, const float* __restrict__ bf,
                        __half* KEb, __half* KEs, __half* VFb, __half* VFs)
{
    const int per = (K_ * HD_) / 4;
    const int i = blockIdx.x * 256 + threadIdx.x;
    const int b = blockIdx.y;
    const int which = blockIdx.z;

    const float* bias = which ? bf : be;
    __half* ob = which ? VFb : KEb;
    __half* os = which ? VFs : KEs;
    const int cols = which ? K_ : HD_;
    const float4* p = (const float4*)(part + (which ? (size_t)8 * K_ * HD_ : 0))
                      + (size_t)b * 4 * per;

    float4 v = p[i];
    float4 v1 = p[per + i], v2 = p[2 * per + i], v3 = p[3 * per + i];
    v.x += v1.x + v2.x + v3.x; v.y += v1.y + v2.y + v3.y;
    v.z += v1.z + v2.z + v3.z; v.w += v1.w + v2.w + v3.w;
    const int e = i * 4;
    if (which) {           // per-column bias
        const int c = e % cols;
        v.x += bias[c]; v.y += bias[c + 1]; v.z += bias[c + 2]; v.w += bias[c + 3];
    } else {               // per-row bias
        const float bb = bias[e / cols];
        v.x += bb; v.y += bb; v.z += bb; v.w += bb;
    }
    uint32_t b0, s0, b1, s1;
    splitf(v.x, v.y, b0, s0);
    splitf(v.z, v.w, b1, s1);
    ((uint2*)ob)[(size_t)b * per + i] = make_uint2(b0, b1);
    ((uint2*)os)[(size_t)b * per + i] = make_uint2(s0, s1);
}

// ==========================================================================
// Fused attention: CTA = (128 rows, head h, batch b), 8 warps
// ==========================================================================
#define QSTR 72
#define VSTR 264
#define OQB 0
#define OKB (128 * QSTR)
#define OKS (OKB + 256 * QSTR)
#define OVB (OKS + 256 * QSTR)
#define OVS (OVB + 64 * VSTR)
#define ATT_SMEM ((OVS + 64 * VSTR) * 2)   // 159744 bytes

__global__ void __launch_bounds__(256, 1)
attn_mma(const __half* __restrict__ Qb, const __half* __restrict__ KEb,
         const __half* __restrict__ KEs, const __half* __restrict__ VFb,
         const __half* __restrict__ VFs, __half* __restrict__ Ob)
{
    extern __shared__ __half sh[];
    const int tid = threadIdx.x, wid = tid >> 5, lane = tid & 31;
    const int b = blockIdx.z, h = blockIdx.y, n0 = blockIdx.x * 128;
    const uint32_t shb = su32(sh);

    const __half* Qgb = Qb  + ((size_t)(b * N_ + n0)) * HD_ + h * D_;
    const __half* Kgb = KEb + ((size_t)b * K_) * HD_ + h * D_;
    const __half* Kgs = KEs + ((size_t)b * K_) * HD_ + h * D_;
    const __half* Vgb = VFb + ((size_t)(b * HD_ + h * D_)) * K_;
    const __half* Vgs = VFs + ((size_t)(b * HD_ + h * D_)) * K_;

#pragma unroll
    for (int p = 0; p < 4; p++) {         // Q: 128 rows x 8 chunks (big only)
        const int id = p * 256 + tid;
        const int r = id >> 3, c = id & 7;
        CP16(shb + OQB * 2 + (r * QSTR + c * 8) * 2, Qgb + (size_t)r * HD_ + c * 8);
    }
#pragma unroll
    for (int p = 0; p < 8; p++) {         // KE: 256 rows x 8 chunks
        const int id = p * 256 + tid;
        const int r = id >> 3, c = id & 7;
        const size_t g = (size_t)r * HD_ + c * 8;
        const uint32_t d = (r * QSTR + c * 8) * 2;
        CP16(shb + OKB * 2 + d, Kgb + g);
        CP16(shb + OKS * 2 + d, Kgs + g);
    }
#pragma unroll
    for (int p = 0; p < 8; p++) {         // VF: 64 rows x 32 chunks
        const int id = p * 256 + tid;
        const int r = id >> 5, c = id & 31;
        const size_t g = (size_t)r * K_ + c * 8;
        const uint32_t d = (r * VSTR + c * 8) * 2;
        CP16(shb + OVB * 2 + d, Vgb + g);
        CP16(shb + OVS * 2 + d, Vgs + g);
    }
    CPCOMMIT();
    CPWAIT(0);
    __syncthreads();

    // ---- scores
    float sacc[32][4];
#pragma unroll
    for (int j = 0; j < 32; j++)
#pragma unroll
        for (int q = 0; q < 4; q++) sacc[j][q] = 0.f;

    const int r0 = wid * 16;
    const uint32_t aoff = ((r0 + (lane & 15)) * QSTR + 8 * (lane >> 4)) * 2;
    const uint32_t boff = (((lane & 7) + 8 * (lane >> 4)) * QSTR + 8 * ((lane >> 3) & 1)) * 2;

#pragma unroll
    for (int ks = 0; ks < 64; ks += 16) {
        uint32_t ab[4];
        LDM4(ab, shb + OQB * 2 + aoff + ks * 2);
#pragma unroll
        for (int np = 0; np < 16; np++) {
            uint32_t kb[4], ksm[4];
            const uint32_t bd = boff + (np * 16 * QSTR + ks) * 2;
            LDM4(kb,  shb + OKB * 2 + bd);
            LDM4(ksm, shb + OKS * 2 + bd);
            // de-chain: both bb-term MMAs (distinct accums), then bs terms
            mma16816(sacc[2 * np],     ab, kb);
            mma16816(sacc[2 * np + 1], ab, kb + 2);
            mma16816(sacc[2 * np],     ab, ksm);
            mma16816(sacc[2 * np + 1], ab, ksm + 2);
        }
    }

    // ---- softmax
    float mx0 = -1e30f, mx1 = -1e30f;
#pragma unroll
    for (int j = 0; j < 32; j++) {
        mx0 = fmaxf(mx0, fmaxf(sacc[j][0], sacc[j][1]));
        mx1 = fmaxf(mx1, fmaxf(sacc[j][2], sacc[j][3]));
    }
    mx0 = fmaxf(mx0, __shfl_xor_sync(0xffffffffu, mx0, 1));
    mx0 = fmaxf(mx0, __shfl_xor_sync(0xffffffffu, mx0, 2));
    mx1 = fmaxf(mx1, __shfl_xor_sync(0xffffffffu, mx1, 1));
    mx1 = fmaxf(mx1, __shfl_xor_sync(0xffffffffu, mx1, 2));
    float sum0 = 0.f, sum1 = 0.f;
#pragma unroll
    for (int j = 0; j < 32; j++) {
        float e0 = __expf((sacc[j][0] - mx0) * 0.125f);
        float e1 = __expf((sacc[j][1] - mx0) * 0.125f);
        float e2 = __expf((sacc[j][2] - mx1) * 0.125f);
        float e3 = __expf((sacc[j][3] - mx1) * 0.125f);
        sacc[j][0] = e0; sacc[j][1] = e1; sacc[j][2] = e2; sacc[j][3] = e3;
        sum0 += e0 + e1; sum1 += e2 + e3;
    }
    sum0 += __shfl_xor_sync(0xffffffffu, sum0, 1);
    sum0 += __shfl_xor_sync(0xffffffffu, sum0, 2);
    sum1 += __shfl_xor_sync(0xffffffffu, sum1, 1);
    sum1 += __shfl_xor_sync(0xffffffffu, sum1, 2);
    const float inv0 = 1.0f / sum0, inv1 = 1.0f / sum1;
#pragma unroll
    for (int j = 0; j < 32; j++) {
        sacc[j][0] *= inv0; sacc[j][1] *= inv0;
        sacc[j][2] *= inv1; sacc[j][3] *= inv1;
    }

    // ---- PV (P as plain fp16)
    float oacc[8][4];
#pragma unroll
    for (int n = 0; n < 8; n++)
#pragma unroll
        for (int q = 0; q < 4; q++) oacc[n][q] = 0.f;

#pragma unroll
    for (int kt = 0; kt < 16; kt++) {
        uint32_t pa[4];
        pa[0] = packh2(sacc[2 * kt][0],     sacc[2 * kt][1]);
        pa[1] = packh2(sacc[2 * kt][2],     sacc[2 * kt][3]);
        pa[2] = packh2(sacc[2 * kt + 1][0], sacc[2 * kt + 1][1]);
        pa[3] = packh2(sacc[2 * kt + 1][2], sacc[2 * kt + 1][3]);
#pragma unroll
        for (int np = 0; np < 4; np++) {
            const uint32_t bd = (((lane & 7) + 8 * (lane >> 4) + np * 16) * VSTR
                                 + kt * 16 + 8 * ((lane >> 3) & 1)) * 2;
            uint32_t vb[4], vs[4];
            LDM4(vb, shb + OVB * 2 + bd);
            LDM4(vs, shb + OVS * 2 + bd);
            mma16816(oacc[2 * np],     pa, vb);
            mma16816(oacc[2 * np + 1], pa, vb + 2);
            mma16816(oacc[2 * np],     pa, vs);
            mma16816(oacc[2 * np + 1], pa, vs + 2);
        }
    }

    // ---- store O (fp16 big only; out-proj uses A = Ob)
    const int orow = n0 + r0 + (lane >> 2);
    const int ocol = h * D_ + 2 * (lane & 3);
    __half* Obp = Ob + ((size_t)b * N_) * HD_;
#pragma unroll
    for (int n = 0; n < 8; n++) {
        *(uint32_t*)&Obp[(size_t)orow * HD_ + ocol + n * 8]       = packh2(oacc[n][0], oacc[n][1]);
        *(uint32_t*)&Obp[(size_t)(orow + 8) * HD_ + ocol + n * 8] = packh2(oacc[n][2], oacc[n][3]);
    }
}

// ==========================================================================
extern "C" void kernel_launch(void* const* d_in, const int* in_sizes, int n_in,
                              void* d_out, int out_size)
{
    const float* X  = (const float*)d_in[0];
    const float* Wq = (const float*)d_in[1];
    const float* Wk = (const float*)d_in[2];
    const float* Wv = (const float*)d_in[3];
    const float* We = (const float*)d_in[4];
    const float* be = (const float*)d_in[5];
    const float* Wf = (const float*)d_in[6];
    const float* bf = (const float*)d_in[7];
    const float* Wo = (const float*)d_in[8];
    const float* bo = (const float*)d_in[9];
    float* out = (float*)d_out;

    __half *Xb, *Xs, *Wqb, *Wqs, *Wkb, *Wks, *Wvb, *Wvs, *Web, *Wes, *Wfb, *Wfs, *Wob, *Wos;
    __half *Qb, *Qs, *Ktb, *Kts, *Vtb, *Vts, *KEbp, *KEsp, *VFbp, *VFsp, *Obp;
    float* Pp;
    cudaGetSymbolAddress((void**)&Xb,  h_Xb);  cudaGetSymbolAddress((void**)&Xs,  h_Xs);
    cudaGetSymbolAddress((void**)&Wqb, h_Wqb); cudaGetSymbolAddress((void**)&Wqs, h_Wqs);
    cudaGetSymbolAddress((void**)&Wkb, h_Wkb); cudaGetSymbolAddress((void**)&Wks, h_Wks);
    cudaGetSymbolAddress((void**)&Wvb, h_Wvb); cudaGetSymbolAddress((void**)&Wvs, h_Wvs);
    cudaGetSymbolAddress((void**)&Web, h_Web); cudaGetSymbolAddress((void**)&Wes, h_Wes);
    cudaGetSymbolAddress((void**)&Wfb, h_Wfb); cudaGetSymbolAddress((void**)&Wfs, h_Wfs);
    cudaGetSymbolAddress((void**)&Wob, h_Wob); cudaGetSymbolAddress((void**)&Wos, h_Wos);
    cudaGetSymbolAddress((void**)&Qb,  h_Qb);  cudaGetSymbolAddress((void**)&Qs,  h_Qs);
    cudaGetSymbolAddress((void**)&Ktb, h_Ktb); cudaGetSymbolAddress((void**)&Kts, h_Kts);
    cudaGetSymbolAddress((void**)&Vtb, h_Vtb); cudaGetSymbolAddress((void**)&Vts, h_Vts);
    cudaGetSymbolAddress((void**)&KEbp, h_KEb); cudaGetSymbolAddress((void**)&KEsp, h_KEs);
    cudaGetSymbolAddress((void**)&VFbp, h_VFb); cudaGetSymbolAddress((void**)&VFsp, h_VFs);
    cudaGetSymbolAddress((void**)&Obp, h_Ob);
    cudaGetSymbolAddress((void**)&Pp,  g_part);

    cudaFuncSetAttribute(qkv_gemm,  cudaFuncAttributeMaxDynamicSharedMemorySize, GEMM_SMEM);
    cudaFuncSetAttribute(kevf_gemm, cudaFuncAttributeMaxDynamicSharedMemorySize, GEMM_SMEM);
    cudaFuncSetAttribute(out_gemm,  cudaFuncAttributeMaxDynamicSharedMemorySize, GEMM_SMEM);
    cudaFuncSetAttribute(attn_mma,  cudaFuncAttributeMaxDynamicSharedMemorySize, ATT_SMEM);

    // 1) split X + all six weights in one launch
    split_all<<<8192 + 6 * 1024, 256>>>(
        X, Xb, Xs,
        Wq, Wqb, Wqs, Wk, Wkb, Wks, Wv, Wvb, Wvs,
        We, Web, Wes, Wf, Wfb, Wfs, Wo, Wob, Wos);

    // 2) merged Q + Kt + Vt (1536 CTAs)
    qkv_gemm<<<1536, 256, GEMM_SMEM>>>(Xb, Xs, Wqb, Wqs, Wkb, Wvb,
                                       Qb, Qs, Ktb, Kts, Vtb, Vts);

    // 3) merged KE + VF split-K partials (256 CTAs)
    kevf_gemm<<<256, 256, GEMM_SMEM>>>(Web, Ktb, Kts, Vtb, Wfb, Wfs, Pp);

    // 4) merged reduce (+bias) -> split halves
    reduce2<<<dim3(256, B_, 2), 256>>>(Pp, be, bf, KEbp, KEsp, VFbp, VFsp);

    // 5) fused attention -> O fp16
    attn_mma<<<dim3(N_ / 128, H_, B_), 256, ATT_SMEM>>>(Qb, KEbp, KEsp, VFbp, VFsp, Obp);

    // 6) out = Ob * (Wo)^T + bo
    out_gemm<<<dim3(8, 64), 256, GEMM_SMEM>>>(Obp, Wob, Wos, bo, out);
}